// round 2
// baseline (speedup 1.0000x reference)
#include <cuda_runtime.h>

#define B_   64
#define T_   64
#define V_   32000
#define E_   512
#define H_   1024
#define G_   (3 * H_)
#define DI_  (E_ + H_)
#define MT_  (B_ * T_)
#define SPLITS 4

// ---------------- scratch (device globals; no allocation) ----------------
__device__ float g_gx[MT_ * G_];          // 50.3 MB: enc gx, then reused for dec word-gx
__device__ float g_hbuf[2][B_ * H_];      // ping-pong hidden state
__device__ float g_ctxg[B_ * G_];         // decoder ctx gate contribution (time-invariant)
__device__ float g_ghp[SPLITS][B_ * G_];  // split-K partials of h @ Whh^T
__device__ float g_states[MT_ * H_];      // decoder hidden states
__device__ int   g_didx[MT_];             // decoder word gather indices

// ---------------- generic NT GEMM, 128x128x16 tile, 256 thr, 8x8/thread ----------------
// C[M,N] = Arow(m) . Brow(n) + bias[n];  Arow = A[gidx[m]] if GATHER else A[m]
template <bool GATHER>
__global__ __launch_bounds__(256) void gemm128_nt(
    const float* __restrict__ A, int lda,
    const int* __restrict__ gidx,
    const float* __restrict__ Bm, int ldb,
    const float* __restrict__ bias,
    float* __restrict__ C, int ldc,
    int M, int N, int K)
{
    __shared__ float As[16][128];
    __shared__ float Bs[16][128];

    const int tid = threadIdx.x;
    const int tx = tid & 15;          // n-group
    const int ty = tid >> 4;          // m-group
    const int m0 = blockIdx.y * 128;
    const int n0 = blockIdx.x * 128;

    // load mapping: idx -> (row = idx>>2, kgroup = idx&3), 2 float4 per thread
    const int am0 = tid >> 2;
    const int am1 = am0 + 64;
    const int ak  = (tid & 3) * 4;

    const int grow0 = m0 + am0, grow1 = m0 + am1;
    const bool av0 = grow0 < M, av1 = grow1 < M;
    const int asrc0 = av0 ? (GATHER ? gidx[grow0] : grow0) : 0;
    const int asrc1 = av1 ? (GATHER ? gidx[grow1] : grow1) : 0;
    const float* Ar0 = A + (size_t)asrc0 * lda;
    const float* Ar1 = A + (size_t)asrc1 * lda;
    const float* Br0 = Bm + (size_t)(n0 + am0) * ldb;
    const float* Br1 = Bm + (size_t)(n0 + am1) * ldb;

    float acc[8][8];
#pragma unroll
    for (int i = 0; i < 8; i++)
#pragma unroll
        for (int j = 0; j < 8; j++) acc[i][j] = 0.f;

    for (int k0 = 0; k0 < K; k0 += 16) {
        float4 a0 = av0 ? *(const float4*)(Ar0 + k0 + ak) : make_float4(0.f, 0.f, 0.f, 0.f);
        float4 a1 = av1 ? *(const float4*)(Ar1 + k0 + ak) : make_float4(0.f, 0.f, 0.f, 0.f);
        float4 b0 = *(const float4*)(Br0 + k0 + ak);
        float4 b1 = *(const float4*)(Br1 + k0 + ak);

        __syncthreads();
        As[ak + 0][am0] = a0.x; As[ak + 1][am0] = a0.y; As[ak + 2][am0] = a0.z; As[ak + 3][am0] = a0.w;
        As[ak + 0][am1] = a1.x; As[ak + 1][am1] = a1.y; As[ak + 2][am1] = a1.z; As[ak + 3][am1] = a1.w;
        Bs[ak + 0][am0] = b0.x; Bs[ak + 1][am0] = b0.y; Bs[ak + 2][am0] = b0.z; Bs[ak + 3][am0] = b0.w;
        Bs[ak + 0][am1] = b1.x; Bs[ak + 1][am1] = b1.y; Bs[ak + 2][am1] = b1.z; Bs[ak + 3][am1] = b1.w;
        __syncthreads();

#pragma unroll
        for (int kk = 0; kk < 16; kk++) {
            float4 aA = *(const float4*)&As[kk][ty * 8];
            float4 aB = *(const float4*)&As[kk][ty * 8 + 4];
            float4 bA = *(const float4*)&Bs[kk][tx * 8];
            float4 bB = *(const float4*)&Bs[kk][tx * 8 + 4];
            float a[8] = {aA.x, aA.y, aA.z, aA.w, aB.x, aB.y, aB.z, aB.w};
            float b[8] = {bA.x, bA.y, bA.z, bA.w, bB.x, bB.y, bB.z, bB.w};
#pragma unroll
            for (int i = 0; i < 8; i++)
#pragma unroll
                for (int j = 0; j < 8; j++) acc[i][j] += a[i] * b[j];
        }
    }

    float bv[8];
#pragma unroll
    for (int j = 0; j < 8; j++) bv[j] = 0.f;
    if (bias) {
#pragma unroll
        for (int j = 0; j < 8; j++) bv[j] = bias[n0 + tx * 8 + j];
    }

#pragma unroll
    for (int i = 0; i < 8; i++) {
        int m = m0 + ty * 8 + i;
        if (m < M) {
            float* crow = C + (size_t)m * ldc + n0 + tx * 8;
            float4 o0 = make_float4(acc[i][0] + bv[0], acc[i][1] + bv[1], acc[i][2] + bv[2], acc[i][3] + bv[3]);
            float4 o1 = make_float4(acc[i][4] + bv[4], acc[i][5] + bv[5], acc[i][6] + bv[6], acc[i][7] + bv[7]);
            *(float4*)(crow)     = o0;
            *(float4*)(crow + 4) = o1;
        }
    }
}

// ---------------- small-M NT GEMM: M fixed 64, 64x32x16 tile, 128 thr, 4x4/thread, split-K ----
// blockIdx.z = k-split; writes C + z*cstride
__global__ __launch_bounds__(128) void gemm64_nt(
    const float* __restrict__ A, int lda,
    const float* __restrict__ Bm, int ldb,
    const float* __restrict__ bias,
    float* __restrict__ C, int ldc, size_t cstride,
    int klen)
{
    __shared__ float As[16][64];
    __shared__ float Bs[16][32];

    const int tid = threadIdx.x;
    const int tx = tid & 7;           // n-group (0..7)
    const int ty = tid >> 3;          // m-group (0..15)
    const int n0 = blockIdx.x * 32;
    const int z  = blockIdx.z;
    const int kbeg = z * klen;

    const int am0 = tid >> 2;         // 0..31
    const int am1 = am0 + 32;
    const int ak  = (tid & 3) * 4;

    const float* Ar0 = A + (size_t)am0 * lda;
    const float* Ar1 = A + (size_t)am1 * lda;
    const float* Br  = Bm + (size_t)(n0 + am0) * ldb;  // am0 in 0..31 == n row

    float acc[4][4];
#pragma unroll
    for (int i = 0; i < 4; i++)
#pragma unroll
        for (int j = 0; j < 4; j++) acc[i][j] = 0.f;

    for (int k0 = kbeg; k0 < kbeg + klen; k0 += 16) {
        float4 a0 = *(const float4*)(Ar0 + k0 + ak);
        float4 a1 = *(const float4*)(Ar1 + k0 + ak);
        float4 b  = *(const float4*)(Br  + k0 + ak);

        __syncthreads();
        As[ak + 0][am0] = a0.x; As[ak + 1][am0] = a0.y; As[ak + 2][am0] = a0.z; As[ak + 3][am0] = a0.w;
        As[ak + 0][am1] = a1.x; As[ak + 1][am1] = a1.y; As[ak + 2][am1] = a1.z; As[ak + 3][am1] = a1.w;
        Bs[ak + 0][am0] = b.x;  Bs[ak + 1][am0] = b.y;  Bs[ak + 2][am0] = b.z;  Bs[ak + 3][am0] = b.w;
        __syncthreads();

#pragma unroll
        for (int kk = 0; kk < 16; kk++) {
            float4 av = *(const float4*)&As[kk][ty * 4];
            float4 bv = *(const float4*)&Bs[kk][tx * 4];
            float a[4] = {av.x, av.y, av.z, av.w};
            float b4[4] = {bv.x, bv.y, bv.z, bv.w};
#pragma unroll
            for (int i = 0; i < 4; i++)
#pragma unroll
                for (int j = 0; j < 4; j++) acc[i][j] += a[i] * b4[j];
        }
    }

    float bv4[4] = {0.f, 0.f, 0.f, 0.f};
    if (bias) {
#pragma unroll
        for (int j = 0; j < 4; j++) bv4[j] = bias[n0 + tx * 4 + j];
    }
    float* cbase = C + (size_t)z * cstride;
#pragma unroll
    for (int i = 0; i < 4; i++) {
        int m = ty * 4 + i;
        float* crow = cbase + (size_t)m * ldc + n0 + tx * 4;
        float4 o = make_float4(acc[i][0] + bv4[0], acc[i][1] + bv4[1],
                               acc[i][2] + bv4[2], acc[i][3] + bv4[3]);
        *(float4*)crow = o;
    }
}

// ---------------- GRU gate: combines gx(+ctx), split-K gh partials + bhh ----------------
template <bool DEC>
__global__ __launch_bounds__(256) void gru_gate(
    const float* __restrict__ gx,
    const float* __restrict__ ctxg,
    const float* __restrict__ bhh,
    const float* __restrict__ hin,
    float* __restrict__ hout,
    float* __restrict__ states,
    int t)
{
    int id = blockIdx.x * 256 + threadIdx.x;   // 0 .. B*H-1
    int b = id >> 10;                          // /H_
    int j = id & (H_ - 1);
    int m = b * T_ + t;

    float s[3], xg[3];
#pragma unroll
    for (int q = 0; q < 3; q++) {
        int col = q * H_ + j;
        float a = bhh[col];
#pragma unroll
        for (int sp = 0; sp < SPLITS; sp++) a += g_ghp[sp][b * G_ + col];
        s[q] = a;
        float x = gx[(size_t)m * G_ + col];
        if (DEC) x += ctxg[b * G_ + col];
        xg[q] = x;
    }
    float r = 1.f / (1.f + expf(-(xg[0] + s[0])));
    float z = 1.f / (1.f + expf(-(xg[1] + s[1])));
    float n = tanhf(xg[2] + r * s[2]);
    float h2 = (1.f - z) * n + z * hin[id];
    hout[id] = h2;
    if (DEC) states[(size_t)m * H_ + j] = h2;
}

__global__ void build_didx(const int* __restrict__ labels) {
    int m = blockIdx.x * 256 + threadIdx.x;
    if (m < MT_) {
        int t = m & (T_ - 1);
        g_didx[m] = (t == 0) ? 1 : labels[m - 1];   // BOS = 1
    }
}

__global__ void bcast_h(const float* __restrict__ dec_init, float* __restrict__ hout) {
    int id = blockIdx.x * 256 + threadIdx.x;
    if (id < B_ * H_) hout[id] = dec_init[id & (H_ - 1)];
}

// ---------------- launch ----------------
extern "C" void kernel_launch(void* const* d_in, const int* in_sizes, int n_in,
                              void* d_out, int out_size)
{
    const int*   x        = (const int*)d_in[0];
    const int*   labels   = (const int*)d_in[1];
    const float* enc_emb  = (const float*)d_in[2];
    const float* enc_Wih  = (const float*)d_in[3];
    const float* enc_Whh  = (const float*)d_in[4];
    const float* enc_bih  = (const float*)d_in[5];
    const float* enc_bhh  = (const float*)d_in[6];
    const float* dec_emb  = (const float*)d_in[7];
    const float* dec_Wih  = (const float*)d_in[8];
    const float* dec_Whh  = (const float*)d_in[9];
    const float* dec_bih  = (const float*)d_in[10];
    const float* dec_bhh  = (const float*)d_in[11];
    const float* dec_init = (const float*)d_in[12];
    const float* lin_W    = (const float*)d_in[13];
    const float* lin_b    = (const float*)d_in[14];
    float* out = (float*)d_out;

    float *gx, *hbuf, *ctxg, *ghp, *states;
    int* didx;
    cudaGetSymbolAddress((void**)&gx, g_gx);
    cudaGetSymbolAddress((void**)&hbuf, g_hbuf);
    cudaGetSymbolAddress((void**)&ctxg, g_ctxg);
    cudaGetSymbolAddress((void**)&ghp, g_ghp);
    cudaGetSymbolAddress((void**)&states, g_states);
    cudaGetSymbolAddress((void**)&didx, g_didx);

    // encoder h0 = 0
    cudaMemsetAsync(hbuf, 0, (size_t)B_ * H_ * sizeof(float));

    // encoder input gates: gx = gather(enc_emb, x) @ enc_Wih^T + enc_bih
    dim3 gEnc(G_ / 128, MT_ / 128);
    gemm128_nt<true><<<gEnc, 256>>>(enc_emb, E_, x, enc_Wih, E_, enc_bih, gx, G_, MT_, G_, E_);

    int cur = 0;
    const size_t HB = (size_t)B_ * H_;
    // encoder recurrence
    for (int t = 0; t < T_; t++) {
        gemm64_nt<<<dim3(G_ / 32, 1, SPLITS), 128>>>(
            hbuf + cur * HB, H_, enc_Whh, H_, nullptr, ghp, G_, (size_t)B_ * G_, H_ / SPLITS);
        gru_gate<false><<<B_ * H_ / 256, 256>>>(
            gx, nullptr, enc_bhh, hbuf + cur * HB, hbuf + (cur ^ 1) * HB, nullptr, t);
        cur ^= 1;
    }

    // ctx gate contribution: ctxg = e_final @ dec_Wih[:, E:]^T   (no bias; bias folded into word GEMM)
    gemm64_nt<<<dim3(G_ / 32, 1, 1), 128>>>(
        hbuf + cur * HB, H_, dec_Wih + E_, DI_, nullptr, ctxg, G_, 0, H_);

    // decoder word input gates
    build_didx<<<MT_ / 256, 256>>>(labels);
    gemm128_nt<true><<<gEnc, 256>>>(dec_emb, E_, didx, dec_Wih, DI_, dec_bih, gx, G_, MT_, G_, E_);

    // decoder h0 = broadcast(dec_init)
    bcast_h<<<B_ * H_ / 256, 256>>>(dec_init, hbuf + cur * HB);

    // decoder recurrence (stores states)
    for (int t = 0; t < T_; t++) {
        gemm64_nt<<<dim3(G_ / 32, 1, SPLITS), 128>>>(
            hbuf + cur * HB, H_, dec_Whh, H_, nullptr, ghp, G_, (size_t)B_ * G_, H_ / SPLITS);
        gru_gate<true><<<B_ * H_ / 256, 256>>>(
            gx, ctxg, dec_bhh, hbuf + cur * HB, hbuf + (cur ^ 1) * HB, states, t);
        cur ^= 1;
    }

    // logits = states @ lin_W^T + lin_b
    dim3 gLog(V_ / 128, MT_ / 128);
    gemm128_nt<false><<<gLog, 256>>>(states, H_, nullptr, lin_W, H_, lin_b, out, V_, MT_, V_, H_);
}

// round 4
// speedup vs baseline: 1.8707x; 1.8707x over previous
#include <cuda_runtime.h>
#include <cuda_bf16.h>
#include <cstdint>

#define B_   64
#define T_   64
#define V_   32000
#define E_   512
#define H_   1024
#define G_   (3 * H_)
#define DI_  (E_ + H_)
#define MT_  (B_ * T_)
#define SPLITS 8

// ---------------- scratch (device globals; no allocation) ----------------
__device__ float g_gx[MT_ * G_];
__device__ float g_hbuf[2][B_ * H_];
__device__ float g_ctxg[B_ * G_];
__device__ float g_ghp[SPLITS][B_ * G_];
__device__ float g_states[MT_ * H_];
__device__ int   g_didx[MT_];
__device__ __nv_bfloat16 g_Ah[MT_ * H_];
__device__ __nv_bfloat16 g_Al[MT_ * H_];
__device__ __nv_bfloat16 g_Bh[(size_t)V_ * H_];
__device__ __nv_bfloat16 g_Bl[(size_t)V_ * H_];

// ================= base-ISA helpers (sm_80+ PTX only; NO tcgen05) =================
__device__ __forceinline__ uint32_t smem_u32(const void* p) {
    uint32_t a;
    asm("{ .reg .u64 t; cvta.to.shared.u64 t, %1; cvt.u32.u64 %0, t; }" : "=r"(a) : "l"(p));
    return a;
}
__device__ __forceinline__ void cpasync16(uint32_t saddr, const void* g) {
    asm volatile("cp.async.cg.shared.global [%0], [%1], 16;" :: "r"(saddr), "l"(g));
}
#define CP_COMMIT() asm volatile("cp.async.commit_group;" ::: "memory")
#define CP_WAIT1()  asm volatile("cp.async.wait_group 1;" ::: "memory")

__device__ __forceinline__ void ldsm4(uint32_t* r, uint32_t addr) {
    asm volatile("ldmatrix.sync.aligned.m8n8.x4.shared.b16 {%0,%1,%2,%3}, [%4];"
                 : "=r"(r[0]), "=r"(r[1]), "=r"(r[2]), "=r"(r[3]) : "r"(addr));
}
__device__ __forceinline__ void mma_bf16(float* d, const uint32_t* a, const uint32_t* b) {
    asm volatile(
        "mma.sync.aligned.m16n8k16.row.col.f32.bf16.bf16.f32 "
        "{%0,%1,%2,%3}, {%4,%5,%6,%7}, {%8,%9}, {%0,%1,%2,%3};"
        : "+f"(d[0]), "+f"(d[1]), "+f"(d[2]), "+f"(d[3])
        : "r"(a[0]), "r"(a[1]), "r"(a[2]), "r"(a[3]), "r"(b[0]), "r"(b[1]));
}

// ================= split fp32 -> bf16 hi/lo =================
__global__ __launch_bounds__(256) void split_bf16(
    const float* __restrict__ src, __nv_bfloat16* __restrict__ hi,
    __nv_bfloat16* __restrict__ lo, int n4)
{
    int i = blockIdx.x * 256 + threadIdx.x;
    if (i >= n4) return;
    float4 v = ((const float4*)src)[i];
    __nv_bfloat16 h0 = __float2bfloat16(v.x);
    __nv_bfloat16 h1 = __float2bfloat16(v.y);
    __nv_bfloat16 h2 = __float2bfloat16(v.z);
    __nv_bfloat16 h3 = __float2bfloat16(v.w);
    __nv_bfloat16 l0 = __float2bfloat16(v.x - __bfloat162float(h0));
    __nv_bfloat16 l1 = __float2bfloat16(v.y - __bfloat162float(h1));
    __nv_bfloat16 l2 = __float2bfloat16(v.z - __bfloat162float(h2));
    __nv_bfloat16 l3 = __float2bfloat16(v.w - __bfloat162float(h3));
    __nv_bfloat162* ph = (__nv_bfloat162*)hi;
    __nv_bfloat162* pl = (__nv_bfloat162*)lo;
    ph[2 * i]     = __nv_bfloat162(h0, h1);
    ph[2 * i + 1] = __nv_bfloat162(h2, h3);
    pl[2 * i]     = __nv_bfloat162(l0, l1);
    pl[2 * i + 1] = __nv_bfloat162(l2, l3);
}

// ================= logits GEMM: mma.sync bf16 3-term split =================
// CTA tile 128x128, k-chunk 32, 2-stage cp.async pipeline.
// smem per stage: 4 tiles (Ah,Al,Bh,Bl) of 128 rows x 32 bf16 (64B rows, swizzled)
#define KCH 32
#define NST (H_ / KCH)               // 32 stages
#define TILE_B  (128 * 64)           // 8KB
#define OFF_AH  0
#define OFF_AL  (TILE_B)
#define OFF_BH  (2 * TILE_B)
#define OFF_BL  (3 * TILE_B)
#define STAGE_B (4 * TILE_B)         // 32KB

// swizzle: row r (0-127), 16B-chunk c (0-3): conflict-free for ldmatrix & cp.async
__device__ __forceinline__ uint32_t swz(int r, int c) {
    return (uint32_t)(r * 64 + ((c ^ ((r >> 1) & 3)) << 4));
}

__global__ __launch_bounds__(256) void logits_hmma(
    const __nv_bfloat16* __restrict__ Ah, const __nv_bfloat16* __restrict__ Al,
    const __nv_bfloat16* __restrict__ Bh, const __nv_bfloat16* __restrict__ Bl,
    const float* __restrict__ bias, float* __restrict__ C)
{
    extern __shared__ char sm[];
    const uint32_t sb = smem_u32(sm);
    const int tid = threadIdx.x;
    const int lane = tid & 31;
    const int wid = tid >> 5;
    const int m0 = blockIdx.x * 128;      // m fast-varying: wave shares B tile via L2
    const int n0 = blockIdx.y * 128;
    const int wm = wid >> 2;              // 0-1
    const int wn = wid & 3;               // 0-3

    // ---- cp.async thread mapping: chunks v=tid and v=tid+256 ----
    const int r0 = tid >> 2, c0 = tid & 3;
    const int r1 = r0 + 64;
    const uint32_t so0 = swz(r0, c0);
    const uint32_t so1 = swz(r1, c0);
    const __nv_bfloat16* gAh0 = Ah + (size_t)(m0 + r0) * H_ + c0 * 8;
    const __nv_bfloat16* gAh1 = Ah + (size_t)(m0 + r1) * H_ + c0 * 8;
    const __nv_bfloat16* gAl0 = Al + (size_t)(m0 + r0) * H_ + c0 * 8;
    const __nv_bfloat16* gAl1 = Al + (size_t)(m0 + r1) * H_ + c0 * 8;
    const __nv_bfloat16* gBh0 = Bh + (size_t)(n0 + r0) * H_ + c0 * 8;
    const __nv_bfloat16* gBh1 = Bh + (size_t)(n0 + r1) * H_ + c0 * 8;
    const __nv_bfloat16* gBl0 = Bl + (size_t)(n0 + r0) * H_ + c0 * 8;
    const __nv_bfloat16* gBl1 = Bl + (size_t)(n0 + r1) * H_ + c0 * 8;

    // ---- ldmatrix lane address components ----
    // A (x4 covers m16 x k16): row = wm*64 + mi*16 + (lane&7) + ((lane>>3)&1)*8 ; c = 2s + (lane>>4)
    int arow[4], axr[4];
#pragma unroll
    for (int mi = 0; mi < 4; mi++) {
        int r = wm * 64 + mi * 16 + (lane & 7) + ((lane >> 3) & 1) * 8;
        arow[mi] = r * 64;
        axr[mi] = (r >> 1) & 3;
    }
    const int acb = (lane >> 4);          // A c-base add
    // B (x4 covers n16 x k16): row = wn*32 + nf2*16 + (lane&7) + ((lane>>4)&1)*8 ; c = 2s + ((lane>>3)&1)
    int brow[2], bxr[2];
#pragma unroll
    for (int nf2 = 0; nf2 < 2; nf2++) {
        int r = wn * 32 + nf2 * 16 + (lane & 7) + ((lane >> 4) & 1) * 8;
        brow[nf2] = r * 64;
        bxr[nf2] = (r >> 1) & 3;
    }
    const int bcb = ((lane >> 3) & 1);

    float acc[4][4][4];
#pragma unroll
    for (int mi = 0; mi < 4; mi++)
#pragma unroll
        for (int nf = 0; nf < 4; nf++)
#pragma unroll
            for (int q = 0; q < 4; q++) acc[mi][nf][q] = 0.f;

    // ---- pipeline ----
#define ISSUE(buf, kb) do { \
        uint32_t s_ = sb + (buf) * STAGE_B; \
        cpasync16(s_ + OFF_AH + so0, gAh0 + (kb)); cpasync16(s_ + OFF_AH + so1, gAh1 + (kb)); \
        cpasync16(s_ + OFF_AL + so0, gAl0 + (kb)); cpasync16(s_ + OFF_AL + so1, gAl1 + (kb)); \
        cpasync16(s_ + OFF_BH + so0, gBh0 + (kb)); cpasync16(s_ + OFF_BH + so1, gBh1 + (kb)); \
        cpasync16(s_ + OFF_BL + so0, gBl0 + (kb)); cpasync16(s_ + OFF_BL + so1, gBl1 + (kb)); \
    } while (0)

    ISSUE(0, 0);
    CP_COMMIT();
    ISSUE(1, KCH);
    CP_COMMIT();

    for (int st = 0; st < NST; st++) {
        CP_WAIT1();
        __syncthreads();
        const uint32_t base = sb + (st & 1) * STAGE_B;

#pragma unroll
        for (int s = 0; s < 2; s++) {
            uint32_t ah[4][4], al[4][4];
#pragma unroll
            for (int mi = 0; mi < 4; mi++) {
                uint32_t off = arow[mi] + ((((2 * s + acb)) ^ axr[mi]) << 4);
                ldsm4(ah[mi], base + OFF_AH + off);
                ldsm4(al[mi], base + OFF_AL + off);
            }
            uint32_t bhf[2][4], blf[2][4];
#pragma unroll
            for (int nf2 = 0; nf2 < 2; nf2++) {
                uint32_t off = brow[nf2] + ((((2 * s + bcb)) ^ bxr[nf2]) << 4);
                ldsm4(bhf[nf2], base + OFF_BH + off);
                ldsm4(blf[nf2], base + OFF_BL + off);
            }
#pragma unroll
            for (int mi = 0; mi < 4; mi++) {
#pragma unroll
                for (int nf = 0; nf < 4; nf++) {
                    const uint32_t* bp = &bhf[nf >> 1][(nf & 1) * 2];
                    const uint32_t* bq = &blf[nf >> 1][(nf & 1) * 2];
                    mma_bf16(acc[mi][nf], ah[mi], bp);
                    mma_bf16(acc[mi][nf], ah[mi], bq);
                    mma_bf16(acc[mi][nf], al[mi], bp);
                }
            }
        }
        __syncthreads();
        if (st + 2 < NST) ISSUE(st & 1, (st + 2) * KCH);
        CP_COMMIT();
    }
#undef ISSUE

    // ---- epilogue ----
    const int erow = m0 + wm * 64 + (lane >> 2);
    const int ecol0 = n0 + wn * 32 + (lane & 3) * 2;
#pragma unroll
    for (int mi = 0; mi < 4; mi++) {
#pragma unroll
        for (int nf = 0; nf < 4; nf++) {
            int col = ecol0 + nf * 8;
            float2 bv = *(const float2*)(bias + col);
            int row = erow + mi * 16;
            float2 o0 = make_float2(acc[mi][nf][0] + bv.x, acc[mi][nf][1] + bv.y);
            float2 o1 = make_float2(acc[mi][nf][2] + bv.x, acc[mi][nf][3] + bv.y);
            *(float2*)(C + (size_t)row * V_ + col) = o0;
            *(float2*)(C + (size_t)(row + 8) * V_ + col) = o1;
        }
    }
}

// ---------------- generic NT GEMM, 128x128x16 tile, 256 thr, 8x8/thread ----------------
template <bool GATHER>
__global__ __launch_bounds__(256) void gemm128_nt(
    const float* __restrict__ A, int lda,
    const int* __restrict__ gidx,
    const float* __restrict__ Bm, int ldb,
    const float* __restrict__ bias,
    float* __restrict__ C, int ldc,
    int M, int N, int K)
{
    __shared__ float As[16][128];
    __shared__ float Bs[16][128];

    const int tid = threadIdx.x;
    const int tx = tid & 15;
    const int ty = tid >> 4;
    const int m0 = blockIdx.y * 128;
    const int n0 = blockIdx.x * 128;

    const int am0 = tid >> 2;
    const int am1 = am0 + 64;
    const int ak  = (tid & 3) * 4;

    const int grow0 = m0 + am0, grow1 = m0 + am1;
    const bool av0 = grow0 < M, av1 = grow1 < M;
    const int asrc0 = av0 ? (GATHER ? gidx[grow0] : grow0) : 0;
    const int asrc1 = av1 ? (GATHER ? gidx[grow1] : grow1) : 0;
    const float* Ar0 = A + (size_t)asrc0 * lda;
    const float* Ar1 = A + (size_t)asrc1 * lda;
    const float* Br0 = Bm + (size_t)(n0 + am0) * ldb;
    const float* Br1 = Bm + (size_t)(n0 + am1) * ldb;

    float acc[8][8];
#pragma unroll
    for (int i = 0; i < 8; i++)
#pragma unroll
        for (int j = 0; j < 8; j++) acc[i][j] = 0.f;

    for (int k0 = 0; k0 < K; k0 += 16) {
        float4 a0 = av0 ? *(const float4*)(Ar0 + k0 + ak) : make_float4(0.f, 0.f, 0.f, 0.f);
        float4 a1 = av1 ? *(const float4*)(Ar1 + k0 + ak) : make_float4(0.f, 0.f, 0.f, 0.f);
        float4 b0 = *(const float4*)(Br0 + k0 + ak);
        float4 b1 = *(const float4*)(Br1 + k0 + ak);

        __syncthreads();
        As[ak + 0][am0] = a0.x; As[ak + 1][am0] = a0.y; As[ak + 2][am0] = a0.z; As[ak + 3][am0] = a0.w;
        As[ak + 0][am1] = a1.x; As[ak + 1][am1] = a1.y; As[ak + 2][am1] = a1.z; As[ak + 3][am1] = a1.w;
        Bs[ak + 0][am0] = b0.x; Bs[ak + 1][am0] = b0.y; Bs[ak + 2][am0] = b0.z; Bs[ak + 3][am0] = b0.w;
        Bs[ak + 0][am1] = b1.x; Bs[ak + 1][am1] = b1.y; Bs[ak + 2][am1] = b1.z; Bs[ak + 3][am1] = b1.w;
        __syncthreads();

#pragma unroll
        for (int kk = 0; kk < 16; kk++) {
            float4 aA = *(const float4*)&As[kk][ty * 8];
            float4 aB = *(const float4*)&As[kk][ty * 8 + 4];
            float4 bA = *(const float4*)&Bs[kk][tx * 8];
            float4 bB = *(const float4*)&Bs[kk][tx * 8 + 4];
            float a[8] = {aA.x, aA.y, aA.z, aA.w, aB.x, aB.y, aB.z, aB.w};
            float b[8] = {bA.x, bA.y, bA.z, bA.w, bB.x, bB.y, bB.z, bB.w};
#pragma unroll
            for (int i = 0; i < 8; i++)
#pragma unroll
                for (int j = 0; j < 8; j++) acc[i][j] += a[i] * b[j];
        }
    }

    float bv[8];
#pragma unroll
    for (int j = 0; j < 8; j++) bv[j] = 0.f;
    if (bias) {
#pragma unroll
        for (int j = 0; j < 8; j++) bv[j] = bias[n0 + tx * 8 + j];
    }

#pragma unroll
    for (int i = 0; i < 8; i++) {
        int m = m0 + ty * 8 + i;
        if (m < M) {
            float* crow = C + (size_t)m * ldc + n0 + tx * 8;
            float4 o0 = make_float4(acc[i][0] + bv[0], acc[i][1] + bv[1], acc[i][2] + bv[2], acc[i][3] + bv[3]);
            float4 o1 = make_float4(acc[i][4] + bv[4], acc[i][5] + bv[5], acc[i][6] + bv[6], acc[i][7] + bv[7]);
            *(float4*)(crow)     = o0;
            *(float4*)(crow + 4) = o1;
        }
    }
}

// ---------------- small-M NT GEMM (recurrence), split-K ----------------
__global__ __launch_bounds__(128) void gemm64_nt(
    const float* __restrict__ A, int lda,
    const float* __restrict__ Bm, int ldb,
    const float* __restrict__ bias,
    float* __restrict__ C, int ldc, size_t cstride,
    int klen)
{
    __shared__ float As[16][64];
    __shared__ float Bs[16][32];

    const int tid = threadIdx.x;
    const int tx = tid & 7;
    const int ty = tid >> 3;
    const int n0 = blockIdx.x * 32;
    const int z  = blockIdx.z;
    const int kbeg = z * klen;

    const int am0 = tid >> 2;
    const int am1 = am0 + 32;
    const int ak  = (tid & 3) * 4;

    const float* Ar0 = A + (size_t)am0 * lda;
    const float* Ar1 = A + (size_t)am1 * lda;
    const float* Br  = Bm + (size_t)(n0 + am0) * ldb;

    float acc[4][4];
#pragma unroll
    for (int i = 0; i < 4; i++)
#pragma unroll
        for (int j = 0; j < 4; j++) acc[i][j] = 0.f;

    for (int k0 = kbeg; k0 < kbeg + klen; k0 += 16) {
        float4 a0 = *(const float4*)(Ar0 + k0 + ak);
        float4 a1 = *(const float4*)(Ar1 + k0 + ak);
        float4 b  = *(const float4*)(Br  + k0 + ak);

        __syncthreads();
        As[ak + 0][am0] = a0.x; As[ak + 1][am0] = a0.y; As[ak + 2][am0] = a0.z; As[ak + 3][am0] = a0.w;
        As[ak + 0][am1] = a1.x; As[ak + 1][am1] = a1.y; As[ak + 2][am1] = a1.z; As[ak + 3][am1] = a1.w;
        Bs[ak + 0][am0] = b.x;  Bs[ak + 1][am0] = b.y;  Bs[ak + 2][am0] = b.z;  Bs[ak + 3][am0] = b.w;
        __syncthreads();

#pragma unroll
        for (int kk = 0; kk < 16; kk++) {
            float4 av = *(const float4*)&As[kk][ty * 4];
            float4 bv = *(const float4*)&Bs[kk][tx * 4];
            float a[4] = {av.x, av.y, av.z, av.w};
            float b4[4] = {bv.x, bv.y, bv.z, bv.w};
#pragma unroll
            for (int i = 0; i < 4; i++)
#pragma unroll
                for (int j = 0; j < 4; j++) acc[i][j] += a[i] * b4[j];
        }
    }

    float bv4[4] = {0.f, 0.f, 0.f, 0.f};
    if (bias) {
#pragma unroll
        for (int j = 0; j < 4; j++) bv4[j] = bias[n0 + tx * 4 + j];
    }
    float* cbase = C + (size_t)z * cstride;
#pragma unroll
    for (int i = 0; i < 4; i++) {
        int m = ty * 4 + i;
        float* crow = cbase + (size_t)m * ldc + n0 + tx * 4;
        float4 o = make_float4(acc[i][0] + bv4[0], acc[i][1] + bv4[1],
                               acc[i][2] + bv4[2], acc[i][3] + bv4[3]);
        *(float4*)crow = o;
    }
}

// ---------------- GRU gate ----------------
template <bool DEC>
__global__ __launch_bounds__(256) void gru_gate(
    const float* __restrict__ gx,
    const float* __restrict__ ctxg,
    const float* __restrict__ bhh,
    const float* __restrict__ hin,
    float* __restrict__ hout,
    float* __restrict__ states,
    int t)
{
    int id = blockIdx.x * 256 + threadIdx.x;
    int b = id >> 10;
    int j = id & (H_ - 1);
    int m = b * T_ + t;

    float s[3], xg[3];
#pragma unroll
    for (int q = 0; q < 3; q++) {
        int col = q * H_ + j;
        float a = bhh[col];
#pragma unroll
        for (int sp = 0; sp < SPLITS; sp++) a += g_ghp[sp][b * G_ + col];
        s[q] = a;
        float x = gx[(size_t)m * G_ + col];
        if (DEC) x += ctxg[b * G_ + col];
        xg[q] = x;
    }
    float r = 1.f / (1.f + expf(-(xg[0] + s[0])));
    float z = 1.f / (1.f + expf(-(xg[1] + s[1])));
    float n = tanhf(xg[2] + r * s[2]);
    float h2 = (1.f - z) * n + z * hin[id];
    hout[id] = h2;
    if (DEC) states[(size_t)m * H_ + j] = h2;
}

__global__ void build_didx(const int* __restrict__ labels) {
    int m = blockIdx.x * 256 + threadIdx.x;
    if (m < MT_) {
        int t = m & (T_ - 1);
        g_didx[m] = (t == 0) ? 1 : labels[m - 1];
    }
}

__global__ void bcast_h(const float* __restrict__ dec_init, float* __restrict__ hout) {
    int id = blockIdx.x * 256 + threadIdx.x;
    if (id < B_ * H_) hout[id] = dec_init[id & (H_ - 1)];
}

// ---------------- launch ----------------
extern "C" void kernel_launch(void* const* d_in, const int* in_sizes, int n_in,
                              void* d_out, int out_size)
{
    const int*   x        = (const int*)d_in[0];
    const int*   labels   = (const int*)d_in[1];
    const float* enc_emb  = (const float*)d_in[2];
    const float* enc_Wih  = (const float*)d_in[3];
    const float* enc_Whh  = (const float*)d_in[4];
    const float* enc_bih  = (const float*)d_in[5];
    const float* enc_bhh  = (const float*)d_in[6];
    const float* dec_emb  = (const float*)d_in[7];
    const float* dec_Wih  = (const float*)d_in[8];
    const float* dec_Whh  = (const float*)d_in[9];
    const float* dec_bih  = (const float*)d_in[10];
    const float* dec_bhh  = (const float*)d_in[11];
    const float* dec_init = (const float*)d_in[12];
    const float* lin_W    = (const float*)d_in[13];
    const float* lin_b    = (const float*)d_in[14];
    float* out = (float*)d_out;

    float *gx, *hbuf, *ctxg, *ghp, *states;
    int* didx;
    __nv_bfloat16 *pAh, *pAl, *pBh, *pBl;
    cudaGetSymbolAddress((void**)&gx, g_gx);
    cudaGetSymbolAddress((void**)&hbuf, g_hbuf);
    cudaGetSymbolAddress((void**)&ctxg, g_ctxg);
    cudaGetSymbolAddress((void**)&ghp, g_ghp);
    cudaGetSymbolAddress((void**)&states, g_states);
    cudaGetSymbolAddress((void**)&didx, g_didx);
    cudaGetSymbolAddress((void**)&pAh, g_Ah);
    cudaGetSymbolAddress((void**)&pAl, g_Al);
    cudaGetSymbolAddress((void**)&pBh, g_Bh);
    cudaGetSymbolAddress((void**)&pBl, g_Bl);

    cudaMemsetAsync(hbuf, 0, (size_t)B_ * H_ * sizeof(float));

    // convert lin_W once (independent of recurrence)
    {
        int n4 = (V_ * H_) / 4;
        split_bf16<<<(n4 + 255) / 256, 256>>>(lin_W, pBh, pBl, n4);
    }

    // encoder input gates
    dim3 gEnc(G_ / 128, MT_ / 128);
    gemm128_nt<true><<<gEnc, 256>>>(enc_emb, E_, x, enc_Wih, E_, enc_bih, gx, G_, MT_, G_, E_);

    int cur = 0;
    const size_t HB = (size_t)B_ * H_;
    for (int t = 0; t < T_; t++) {
        gemm64_nt<<<dim3(G_ / 32, 1, SPLITS), 128>>>(
            hbuf + cur * HB, H_, enc_Whh, H_, nullptr, ghp, G_, (size_t)B_ * G_, H_ / SPLITS);
        gru_gate<false><<<B_ * H_ / 256, 256>>>(
            gx, nullptr, enc_bhh, hbuf + cur * HB, hbuf + (cur ^ 1) * HB, nullptr, t);
        cur ^= 1;
    }

    gemm64_nt<<<dim3(G_ / 32, 1, 1), 128>>>(
        hbuf + cur * HB, H_, dec_Wih + E_, DI_, nullptr, ctxg, G_, 0, H_);

    build_didx<<<MT_ / 256, 256>>>(labels);
    gemm128_nt<true><<<gEnc, 256>>>(dec_emb, E_, didx, dec_Wih, DI_, dec_bih, gx, G_, MT_, G_, E_);

    bcast_h<<<B_ * H_ / 256, 256>>>(dec_init, hbuf + cur * HB);

    for (int t = 0; t < T_; t++) {
        gemm64_nt<<<dim3(G_ / 32, 1, SPLITS), 128>>>(
            hbuf + cur * HB, H_, dec_Whh, H_, nullptr, ghp, G_, (size_t)B_ * G_, H_ / SPLITS);
        gru_gate<true><<<B_ * H_ / 256, 256>>>(
            gx, ctxg, dec_bhh, hbuf + cur * HB, hbuf + (cur ^ 1) * HB, states, t);
        cur ^= 1;
    }

    // split states to bf16 hi/lo
    {
        int n4 = (MT_ * H_) / 4;
        split_bf16<<<(n4 + 255) / 256, 256>>>(states, pAh, pAl, n4);
    }

    // logits via HMMA bf16 3-term split GEMM
    {
        int smem_bytes = 2 * STAGE_B;   // 64KB
        cudaFuncSetAttribute(logits_hmma, cudaFuncAttributeMaxDynamicSharedMemorySize, smem_bytes);
        dim3 grid(MT_ / 128, V_ / 128); // (32, 250), m fast
        logits_hmma<<<grid, 256, smem_bytes>>>(pAh, pAl, pBh, pBl, lin_b, out);
    }
}

// round 5
// speedup vs baseline: 2.5485x; 1.3623x over previous
#include <cuda_runtime.h>
#include <cuda_bf16.h>
#include <cstdint>

#define B_   64
#define T_   64
#define V_   32000
#define E_   512
#define H_   1024
#define G_   (3 * H_)
#define DI_  (E_ + H_)
#define MT_  (B_ * T_)
#define JC   16            // h-columns per CTA in recurrence
#define NCTA 64
#define RKC  64            // recurrence k-chunk
#define RNCH (H_ / RKC)    // 16

// ---------------- scratch (device globals; no allocation) ----------------
__device__ float g_gx[MT_ * G_];
__device__ float g_ctxg[B_ * G_];
__device__ float g_states[MT_ * H_];
__device__ float g_hfin[B_ * H_];
__device__ int   g_didx[MT_];
__device__ int   g_bar;
__device__ __nv_bfloat16 g_hb[2][2][B_ * H_];        // [pp][hi/lo]
__device__ __nv_bfloat16 g_Ah[MT_ * H_];
__device__ __nv_bfloat16 g_Al[MT_ * H_];
__device__ __nv_bfloat16 g_Bh[(size_t)V_ * H_];
__device__ __nv_bfloat16 g_Bl[(size_t)V_ * H_];
__device__ __nv_bfloat16 g_WencH[NCTA * 48 * H_];
__device__ __nv_bfloat16 g_WencL[NCTA * 48 * H_];
__device__ __nv_bfloat16 g_WdecH[NCTA * 48 * H_];
__device__ __nv_bfloat16 g_WdecL[NCTA * 48 * H_];

// ================= base-ISA helpers (sm_80+ PTX only) =================
__device__ __forceinline__ uint32_t smem_u32(const void* p) {
    uint32_t a;
    asm("{ .reg .u64 t; cvta.to.shared.u64 t, %1; cvt.u32.u64 %0, t; }" : "=r"(a) : "l"(p));
    return a;
}
__device__ __forceinline__ void cpasync16(uint32_t saddr, const void* g) {
    asm volatile("cp.async.cg.shared.global [%0], [%1], 16;" :: "r"(saddr), "l"(g));
}
#define CP_COMMIT() asm volatile("cp.async.commit_group;" ::: "memory")
#define CP_WAIT1()  asm volatile("cp.async.wait_group 1;" ::: "memory")

__device__ __forceinline__ void ldsm4(uint32_t* r, uint32_t addr) {
    asm volatile("ldmatrix.sync.aligned.m8n8.x4.shared.b16 {%0,%1,%2,%3}, [%4];"
                 : "=r"(r[0]), "=r"(r[1]), "=r"(r[2]), "=r"(r[3]) : "r"(addr));
}
__device__ __forceinline__ void ldsm2(uint32_t* r, uint32_t addr) {
    asm volatile("ldmatrix.sync.aligned.m8n8.x2.shared.b16 {%0,%1}, [%2];"
                 : "=r"(r[0]), "=r"(r[1]) : "r"(addr));
}
__device__ __forceinline__ void mma_bf16(float* d, const uint32_t* a, const uint32_t* b) {
    asm volatile(
        "mma.sync.aligned.m16n8k16.row.col.f32.bf16.bf16.f32 "
        "{%0,%1,%2,%3}, {%4,%5,%6,%7}, {%8,%9}, {%0,%1,%2,%3};"
        : "+f"(d[0]), "+f"(d[1]), "+f"(d[2]), "+f"(d[3])
        : "r"(a[0]), "r"(a[1]), "r"(a[2]), "r"(a[3]), "r"(b[0]), "r"(b[1]));
}

// ================= conversion kernels =================
__global__ __launch_bounds__(256) void split_bf16(
    const float* __restrict__ src, __nv_bfloat16* __restrict__ hi,
    __nv_bfloat16* __restrict__ lo, int n4)
{
    int i = blockIdx.x * 256 + threadIdx.x;
    if (i >= n4) return;
    float4 v = ((const float4*)src)[i];
    __nv_bfloat16 h0 = __float2bfloat16(v.x), h1 = __float2bfloat16(v.y);
    __nv_bfloat16 h2 = __float2bfloat16(v.z), h3 = __float2bfloat16(v.w);
    __nv_bfloat16 l0 = __float2bfloat16(v.x - __bfloat162float(h0));
    __nv_bfloat16 l1 = __float2bfloat16(v.y - __bfloat162float(h1));
    __nv_bfloat16 l2 = __float2bfloat16(v.z - __bfloat162float(h2));
    __nv_bfloat16 l3 = __float2bfloat16(v.w - __bfloat162float(h3));
    __nv_bfloat162* ph = (__nv_bfloat162*)hi;
    __nv_bfloat162* pl = (__nv_bfloat162*)lo;
    ph[2 * i]     = __nv_bfloat162(h0, h1);
    ph[2 * i + 1] = __nv_bfloat162(h2, h3);
    pl[2 * i]     = __nv_bfloat162(l0, l1);
    pl[2 * i + 1] = __nv_bfloat162(l2, l3);
}

// gather embedding rows (E_=512 floats) and split; grid = MT_, 128 thr
__global__ __launch_bounds__(128) void gather_split(
    const float* __restrict__ emb, const int* __restrict__ idx,
    __nv_bfloat16* __restrict__ hi, __nv_bfloat16* __restrict__ lo)
{
    int m = blockIdx.x;
    const float* src = emb + (size_t)idx[m] * E_;
    int c = threadIdx.x;                   // 128 float4 = 512
    float4 v = ((const float4*)src)[c];
    __nv_bfloat16 h0 = __float2bfloat16(v.x), h1 = __float2bfloat16(v.y);
    __nv_bfloat16 h2 = __float2bfloat16(v.z), h3 = __float2bfloat16(v.w);
    __nv_bfloat16 l0 = __float2bfloat16(v.x - __bfloat162float(h0));
    __nv_bfloat16 l1 = __float2bfloat16(v.y - __bfloat162float(h1));
    __nv_bfloat16 l2 = __float2bfloat16(v.z - __bfloat162float(h2));
    __nv_bfloat16 l3 = __float2bfloat16(v.w - __bfloat162float(h3));
    size_t o = (size_t)m * E_ + c * 4;
    __nv_bfloat162* ph = (__nv_bfloat162*)(hi + o);
    __nv_bfloat162* pl = (__nv_bfloat162*)(lo + o);
    ph[0] = __nv_bfloat162(h0, h1); ph[1] = __nv_bfloat162(h2, h3);
    pl[0] = __nv_bfloat162(l0, l1); pl[1] = __nv_bfloat162(l2, l3);
}

// split rows with source stride (compacting dec_Wih word part); grid = nrows, 128 thr
__global__ __launch_bounds__(128) void split_stride(
    const float* __restrict__ src, int ld,
    __nv_bfloat16* __restrict__ hi, __nv_bfloat16* __restrict__ lo, int kd)
{
    int row = blockIdx.x;
    const float* s = src + (size_t)row * ld;
    for (int c = threadIdx.x; c < kd / 4; c += 128) {
        float4 v = ((const float4*)s)[c];
        __nv_bfloat16 h0 = __float2bfloat16(v.x), h1 = __float2bfloat16(v.y);
        __nv_bfloat16 h2 = __float2bfloat16(v.z), h3 = __float2bfloat16(v.w);
        __nv_bfloat16 l0 = __float2bfloat16(v.x - __bfloat162float(h0));
        __nv_bfloat16 l1 = __float2bfloat16(v.y - __bfloat162float(h1));
        __nv_bfloat16 l2 = __float2bfloat16(v.z - __bfloat162float(h2));
        __nv_bfloat16 l3 = __float2bfloat16(v.w - __bfloat162float(h3));
        size_t o = (size_t)row * kd + c * 4;
        __nv_bfloat162* ph = (__nv_bfloat162*)(hi + o);
        __nv_bfloat162* pl = (__nv_bfloat162*)(lo + o);
        ph[0] = __nv_bfloat162(h0, h1); ph[1] = __nv_bfloat162(h2, h3);
        pl[0] = __nv_bfloat162(l0, l1); pl[1] = __nv_bfloat162(l2, l3);
    }
}

// rearrange+split Whh: dst[cta][l][k], l = gate*16+jj maps src row gate*H + cta*16 + jj
__global__ __launch_bounds__(256) void whh_split(
    const float* __restrict__ W, __nv_bfloat16* __restrict__ hi,
    __nv_bfloat16* __restrict__ lo)
{
    int cta = blockIdx.x, l = blockIdx.y;
    int g = l >> 4, jj = l & 15;
    const float* s = W + (size_t)(g * H_ + cta * JC + jj) * H_;
    size_t drow = ((size_t)cta * 48 + l) * H_;
    int c = threadIdx.x;                   // 256 float4 = 1024
    float4 v = ((const float4*)s)[c];
    __nv_bfloat16 h0 = __float2bfloat16(v.x), h1 = __float2bfloat16(v.y);
    __nv_bfloat16 h2 = __float2bfloat16(v.z), h3 = __float2bfloat16(v.w);
    __nv_bfloat16 l0 = __float2bfloat16(v.x - __bfloat162float(h0));
    __nv_bfloat16 l1 = __float2bfloat16(v.y - __bfloat162float(h1));
    __nv_bfloat16 l2 = __float2bfloat16(v.z - __bfloat162float(h2));
    __nv_bfloat16 l3 = __float2bfloat16(v.w - __bfloat162float(h3));
    __nv_bfloat162* ph = (__nv_bfloat162*)(hi + drow + c * 4);
    __nv_bfloat162* pl = (__nv_bfloat162*)(lo + drow + c * 4);
    ph[0] = __nv_bfloat162(h0, h1); ph[1] = __nv_bfloat162(h2, h3);
    pl[0] = __nv_bfloat162(l0, l1); pl[1] = __nv_bfloat162(l2, l3);
}

__global__ void build_didx(const int* __restrict__ labels) {
    int m = blockIdx.x * 256 + threadIdx.x;
    if (m < MT_) {
        int t = m & (T_ - 1);
        g_didx[m] = (t == 0) ? 1 : labels[m - 1];
    }
}

// ================= HMMA NT GEMM (bf16 3-term split), templated on K =================
// CTA tile 128x128, k-chunk 32, 2-stage cp.async pipeline. M fast-varying grid.x.
#define KCH 32
#define TILE_B  (128 * 64)
#define OFF_AH  0
#define OFF_AL  (TILE_B)
#define OFF_BH  (2 * TILE_B)
#define OFF_BL  (3 * TILE_B)
#define STAGE_B (4 * TILE_B)    // 32KB

__device__ __forceinline__ uint32_t swz(int r, int c) {
    return (uint32_t)(r * 64 + ((c ^ ((r >> 1) & 3)) << 4));
}

template <int KD>
__global__ __launch_bounds__(256) void hmma_nt(
    const __nv_bfloat16* __restrict__ Ah, const __nv_bfloat16* __restrict__ Al,
    const __nv_bfloat16* __restrict__ Bh, const __nv_bfloat16* __restrict__ Bl,
    const float* __restrict__ bias, float* __restrict__ C, int ldc)
{
    constexpr int NST = KD / KCH;
    extern __shared__ char sm[];
    const uint32_t sb = smem_u32(sm);
    const int tid = threadIdx.x;
    const int lane = tid & 31;
    const int wid = tid >> 5;
    const int m0 = blockIdx.x * 128;
    const int n0 = blockIdx.y * 128;
    const int wm = wid >> 2;
    const int wn = wid & 3;

    const int r0 = tid >> 2, c0 = tid & 3;
    const int r1 = r0 + 64;
    const uint32_t so0 = swz(r0, c0);
    const uint32_t so1 = swz(r1, c0);
    const __nv_bfloat16* gAh0 = Ah + (size_t)(m0 + r0) * KD + c0 * 8;
    const __nv_bfloat16* gAh1 = Ah + (size_t)(m0 + r1) * KD + c0 * 8;
    const __nv_bfloat16* gAl0 = Al + (size_t)(m0 + r0) * KD + c0 * 8;
    const __nv_bfloat16* gAl1 = Al + (size_t)(m0 + r1) * KD + c0 * 8;
    const __nv_bfloat16* gBh0 = Bh + (size_t)(n0 + r0) * KD + c0 * 8;
    const __nv_bfloat16* gBh1 = Bh + (size_t)(n0 + r1) * KD + c0 * 8;
    const __nv_bfloat16* gBl0 = Bl + (size_t)(n0 + r0) * KD + c0 * 8;
    const __nv_bfloat16* gBl1 = Bl + (size_t)(n0 + r1) * KD + c0 * 8;

    int arow[4], axr[4];
#pragma unroll
    for (int mi = 0; mi < 4; mi++) {
        int r = wm * 64 + mi * 16 + (lane & 7) + ((lane >> 3) & 1) * 8;
        arow[mi] = r * 64;
        axr[mi] = (r >> 1) & 3;
    }
    const int acb = (lane >> 4);
    int brow[2], bxr[2];
#pragma unroll
    for (int nf2 = 0; nf2 < 2; nf2++) {
        int r = wn * 32 + nf2 * 16 + (lane & 7) + ((lane >> 4) & 1) * 8;
        brow[nf2] = r * 64;
        bxr[nf2] = (r >> 1) & 3;
    }
    const int bcb = ((lane >> 3) & 1);

    float acc[4][4][4];
#pragma unroll
    for (int mi = 0; mi < 4; mi++)
#pragma unroll
        for (int nf = 0; nf < 4; nf++)
#pragma unroll
            for (int q = 0; q < 4; q++) acc[mi][nf][q] = 0.f;

#define ISSUE(buf, kb) do { \
        uint32_t s_ = sb + (buf) * STAGE_B; \
        cpasync16(s_ + OFF_AH + so0, gAh0 + (kb)); cpasync16(s_ + OFF_AH + so1, gAh1 + (kb)); \
        cpasync16(s_ + OFF_AL + so0, gAl0 + (kb)); cpasync16(s_ + OFF_AL + so1, gAl1 + (kb)); \
        cpasync16(s_ + OFF_BH + so0, gBh0 + (kb)); cpasync16(s_ + OFF_BH + so1, gBh1 + (kb)); \
        cpasync16(s_ + OFF_BL + so0, gBl0 + (kb)); cpasync16(s_ + OFF_BL + so1, gBl1 + (kb)); \
    } while (0)

    ISSUE(0, 0);
    CP_COMMIT();
    ISSUE(1, KCH);
    CP_COMMIT();

    for (int st = 0; st < NST; st++) {
        CP_WAIT1();
        __syncthreads();
        const uint32_t base = sb + (st & 1) * STAGE_B;

#pragma unroll
        for (int s = 0; s < 2; s++) {
            uint32_t ah[4][4], al[4][4];
#pragma unroll
            for (int mi = 0; mi < 4; mi++) {
                uint32_t off = arow[mi] + ((((2 * s + acb)) ^ axr[mi]) << 4);
                ldsm4(ah[mi], base + OFF_AH + off);
                ldsm4(al[mi], base + OFF_AL + off);
            }
            uint32_t bhf[2][4], blf[2][4];
#pragma unroll
            for (int nf2 = 0; nf2 < 2; nf2++) {
                uint32_t off = brow[nf2] + ((((2 * s + bcb)) ^ bxr[nf2]) << 4);
                ldsm4(bhf[nf2], base + OFF_BH + off);
                ldsm4(blf[nf2], base + OFF_BL + off);
            }
#pragma unroll
            for (int mi = 0; mi < 4; mi++) {
#pragma unroll
                for (int nf = 0; nf < 4; nf++) {
                    const uint32_t* bp = &bhf[nf >> 1][(nf & 1) * 2];
                    const uint32_t* bq = &blf[nf >> 1][(nf & 1) * 2];
                    mma_bf16(acc[mi][nf], ah[mi], bp);
                    mma_bf16(acc[mi][nf], ah[mi], bq);
                    mma_bf16(acc[mi][nf], al[mi], bp);
                }
            }
        }
        __syncthreads();
        if (st + 2 < NST) ISSUE(st & 1, (st + 2) * KCH);
        CP_COMMIT();
    }
#undef ISSUE

    const int erow = m0 + wm * 64 + (lane >> 2);
    const int ecol0 = n0 + wn * 32 + (lane & 3) * 2;
#pragma unroll
    for (int mi = 0; mi < 4; mi++) {
#pragma unroll
        for (int nf = 0; nf < 4; nf++) {
            int col = ecol0 + nf * 8;
            float2 bv = *(const float2*)(bias + col);
            int row = erow + mi * 16;
            float2 o0 = make_float2(acc[mi][nf][0] + bv.x, acc[mi][nf][1] + bv.y);
            float2 o1 = make_float2(acc[mi][nf][2] + bv.x, acc[mi][nf][3] + bv.y);
            *(float2*)(C + (size_t)row * ldc + col) = o0;
            *(float2*)(C + (size_t)(row + 8) * ldc + col) = o1;
        }
    }
}

// ================= persistent fused GRU recurrence =================
// 64 CTAs (one per 16 h-columns), 256 threads, 64 steps with grid barrier.
// Per step: gh[64x48] = h[64x1024] @ WhhSlice[48x1024]^T (bf16 3-term HMMA), then gate.
// smem: 2 stages x (Ah 8K | Al 8K | Bh 6K | Bl 6K) + C[64x52]f32 + h_s[64x16]f32 + bhh[48]
#define RST_B 28672
#define SC_OFF (2 * RST_B)
#define HS_OFF (SC_OFF + 64 * 52 * 4)
#define BH_OFF (HS_OFF + 64 * JC * 4)
#define SMEM_REC (BH_OFF + 48 * 4 + 16)

__device__ __forceinline__ uint32_t rswz(int r, int c) {   // row*128B, 8x16B chunks
    return (uint32_t)(r * 128 + ((c ^ (r & 7)) << 4));
}

template <bool DEC>
__global__ __launch_bounds__(256) void recur(
    const __nv_bfloat16* __restrict__ Wh, const __nv_bfloat16* __restrict__ Wl,
    const float* __restrict__ gx, const float* __restrict__ bhh,
    const float* __restrict__ ctxg, const float* __restrict__ dec_init)
{
    extern __shared__ char sm[];
    const uint32_t sb = smem_u32(sm);
    float* sC   = (float*)(sm + SC_OFF);
    float* h_s  = (float*)(sm + HS_OFF);
    float* bhhs = (float*)(sm + BH_OFF);

    const int tid = threadIdx.x;
    const int lane = tid & 31;
    const int wid = tid >> 5;
    const int cta = blockIdx.x;
    const int j0 = cta * JC;

    const __nv_bfloat16* wbh = Wh + (size_t)cta * 48 * H_;
    const __nv_bfloat16* wbl = Wl + (size_t)cta * 48 * H_;

    // warp layout: wm = wid>>1 (m-tile of 16 rows), wh = wid&1 (24 n-cols)
    const int wm = wid >> 1;
    const int wh = wid & 1;
    const int ar = wm * 16 + (lane & 15);
    const int aca = lane >> 4;
    const int br_ = lane & 7;
    const int bca = (lane >> 3) & 1;

    // ---- init h, bhh ----
    if (tid < 48) bhhs[tid] = bhh[(tid >> 4) * H_ + j0 + (tid & 15)];
#pragma unroll
    for (int it = 0; it < 4; it++) {
        int item = tid + it * 256;
        int b = item >> 4, jj = item & 15;
        float h0 = DEC ? dec_init[j0 + jj] : 0.f;
        h_s[item] = h0;
        __nv_bfloat16 hh = __float2bfloat16(h0);
        __nv_bfloat16 hl = __float2bfloat16(h0 - __bfloat162float(hh));
        g_hb[0][0][b * H_ + j0 + jj] = hh;
        g_hb[0][1][b * H_ + j0 + jj] = hl;
    }
    __syncthreads();
    // grid barrier #1
    if (tid == 0) {
        __threadfence();
        atomicAdd(&g_bar, 1);
        volatile int* vb = &g_bar;
        while (*vb < NCTA) __nanosleep(64);
        __threadfence();
    }
    __syncthreads();

    for (int t = 0; t < T_; t++) {
        const int pp = t & 1;
        const __nv_bfloat16* hbh = g_hb[pp][0];
        const __nv_bfloat16* hbl = g_hb[pp][1];

#define RISSUE(buf, kc) do { \
            uint32_t s_ = sb + (buf) * (uint32_t)RST_B; \
            const __nv_bfloat16* pah = hbh + (kc) * RKC; \
            const __nv_bfloat16* pal = hbl + (kc) * RKC; \
            const __nv_bfloat16* pbh = wbh + (kc) * RKC; \
            const __nv_bfloat16* pbl = wbl + (kc) * RKC; \
            _Pragma("unroll") \
            for (int i_ = 0; i_ < 2; i_++) { \
                int v_ = tid + i_ * 256; int r_ = v_ >> 3, c_ = v_ & 7; \
                uint32_t so_ = rswz(r_, c_); \
                cpasync16(s_ + so_,          pah + r_ * H_ + c_ * 8); \
                cpasync16(s_ + 8192u + so_,  pal + r_ * H_ + c_ * 8); \
                if (v_ < 384) { \
                    cpasync16(s_ + 16384u + so_, pbh + r_ * H_ + c_ * 8); \
                    cpasync16(s_ + 22528u + so_, pbl + r_ * H_ + c_ * 8); \
                } \
            } \
        } while (0)

        float acc[3][4];
#pragma unroll
        for (int nt = 0; nt < 3; nt++)
#pragma unroll
            for (int q = 0; q < 4; q++) acc[nt][q] = 0.f;

        RISSUE(0, 0); CP_COMMIT();
        RISSUE(1, 1); CP_COMMIT();

        for (int kc = 0; kc < RNCH; kc++) {
            CP_WAIT1();
            __syncthreads();
            const uint32_t base = sb + (kc & 1) * (uint32_t)RST_B;
#pragma unroll
            for (int s = 0; s < 4; s++) {
                uint32_t aH[4], aL[4];
                uint32_t offA = (uint32_t)(ar * 128 + (((2 * s + aca) ^ (ar & 7)) << 4));
                ldsm4(aH, base + offA);
                ldsm4(aL, base + 8192u + offA);
#pragma unroll
                for (int nt = 0; nt < 3; nt++) {
                    int rb0 = wh * 24 + nt * 8 + br_;
                    uint32_t offB = (uint32_t)(rb0 * 128 + (((2 * s + bca) ^ (rb0 & 7)) << 4));
                    uint32_t bH[2], bL[2];
                    ldsm2(bH, base + 16384u + offB);
                    ldsm2(bL, base + 22528u + offB);
                    mma_bf16(acc[nt], aH, bH);
                    mma_bf16(acc[nt], aH, bL);
                    mma_bf16(acc[nt], aL, bH);
                }
            }
            __syncthreads();
            if (kc + 2 < RNCH) RISSUE(kc & 1, kc + 2);
            CP_COMMIT();
        }
#undef RISSUE

        // stage gh to smem
        {
            int crow = wm * 16 + (lane >> 2);
            int ccol = wh * 24 + (lane & 3) * 2;
#pragma unroll
            for (int nt = 0; nt < 3; nt++) {
                int cc = ccol + nt * 8;
                *(float2*)&sC[crow * 52 + cc]       = make_float2(acc[nt][0], acc[nt][1]);
                *(float2*)&sC[(crow + 8) * 52 + cc] = make_float2(acc[nt][2], acc[nt][3]);
            }
        }
        __syncthreads();

        // gate
        __nv_bfloat16* nhh = g_hb[pp ^ 1][0];
        __nv_bfloat16* nhl = g_hb[pp ^ 1][1];
#pragma unroll
        for (int it = 0; it < 4; it++) {
            int item = tid + it * 256;
            int b = item >> 4, jj = item & 15;
            float ghr = sC[b * 52 + jj]      + bhhs[jj];
            float ghz = sC[b * 52 + 16 + jj] + bhhs[16 + jj];
            float ghn = sC[b * 52 + 32 + jj] + bhhs[32 + jj];
            const float* gxm = gx + (size_t)(b * T_ + t) * G_;
            float xr = gxm[j0 + jj];
            float xz = gxm[H_ + j0 + jj];
            float xn = gxm[2 * H_ + j0 + jj];
            if (DEC) {
                const float* cg = ctxg + (size_t)b * G_;
                xr += cg[j0 + jj]; xz += cg[H_ + j0 + jj]; xn += cg[2 * H_ + j0 + jj];
            }
            float r = 1.f / (1.f + expf(-(xr + ghr)));
            float z = 1.f / (1.f + expf(-(xz + ghz)));
            float n = tanhf(xn + r * ghn);
            float h2 = (1.f - z) * n + z * h_s[item];
            h_s[item] = h2;
            __nv_bfloat16 hh = __float2bfloat16(h2);
            __nv_bfloat16 hl = __float2bfloat16(h2 - __bfloat162float(hh));
            int gcol = b * H_ + j0 + jj;
            nhh[gcol] = hh;
            nhl[gcol] = hl;
            if (DEC) g_states[(size_t)(b * T_ + t) * H_ + j0 + jj] = h2;
            else if (t == T_ - 1) g_hfin[gcol] = h2;
        }
        __syncthreads();
        // grid barrier
        if (tid == 0) {
            __threadfence();
            atomicAdd(&g_bar, 1);
            int target = NCTA * (t + 2);
            volatile int* vb = &g_bar;
            while (*vb < target) __nanosleep(64);
            __threadfence();
        }
        __syncthreads();
    }
}

// ---------------- small fp32 NT GEMM for ctxg (single launch) ----------------
__global__ __launch_bounds__(128) void gemm64_nt(
    const float* __restrict__ A, int lda,
    const float* __restrict__ Bm, int ldb,
    float* __restrict__ C, int ldc, int klen)
{
    __shared__ float As[16][64];
    __shared__ float Bs[16][32];

    const int tid = threadIdx.x;
    const int tx = tid & 7;
    const int ty = tid >> 3;
    const int n0 = blockIdx.x * 32;

    const int am0 = tid >> 2;
    const int am1 = am0 + 32;
    const int ak  = (tid & 3) * 4;

    const float* Ar0 = A + (size_t)am0 * lda;
    const float* Ar1 = A + (size_t)am1 * lda;
    const float* Br  = Bm + (size_t)(n0 + am0) * ldb;

    float acc[4][4];
#pragma unroll
    for (int i = 0; i < 4; i++)
#pragma unroll
        for (int j = 0; j < 4; j++) acc[i][j] = 0.f;

    for (int k0 = 0; k0 < klen; k0 += 16) {
        float4 a0 = *(const float4*)(Ar0 + k0 + ak);
        float4 a1 = *(const float4*)(Ar1 + k0 + ak);
        float4 b  = *(const float4*)(Br  + k0 + ak);

        __syncthreads();
        As[ak + 0][am0] = a0.x; As[ak + 1][am0] = a0.y; As[ak + 2][am0] = a0.z; As[ak + 3][am0] = a0.w;
        As[ak + 0][am1] = a1.x; As[ak + 1][am1] = a1.y; As[ak + 2][am1] = a1.z; As[ak + 3][am1] = a1.w;
        Bs[ak + 0][am0] = b.x;  Bs[ak + 1][am0] = b.y;  Bs[ak + 2][am0] = b.z;  Bs[ak + 3][am0] = b.w;
        __syncthreads();

#pragma unroll
        for (int kk = 0; kk < 16; kk++) {
            float4 av = *(const float4*)&As[kk][ty * 4];
            float4 bv = *(const float4*)&Bs[kk][tx * 4];
            float a[4] = {av.x, av.y, av.z, av.w};
            float b4[4] = {bv.x, bv.y, bv.z, bv.w};
#pragma unroll
            for (int i = 0; i < 4; i++)
#pragma unroll
                for (int j = 0; j < 4; j++) acc[i][j] += a[i] * b4[j];
        }
    }

#pragma unroll
    for (int i = 0; i < 4; i++) {
        int m = ty * 4 + i;
        float* crow = C + (size_t)m * ldc + n0 + tx * 4;
        *(float4*)crow = make_float4(acc[i][0], acc[i][1], acc[i][2], acc[i][3]);
    }
}

// ---------------- launch ----------------
extern "C" void kernel_launch(void* const* d_in, const int* in_sizes, int n_in,
                              void* d_out, int out_size)
{
    const int*   x        = (const int*)d_in[0];
    const int*   labels   = (const int*)d_in[1];
    const float* enc_emb  = (const float*)d_in[2];
    const float* enc_Wih  = (const float*)d_in[3];
    const float* enc_Whh  = (const float*)d_in[4];
    const float* enc_bih  = (const float*)d_in[5];
    const float* enc_bhh  = (const float*)d_in[6];
    const float* dec_emb  = (const float*)d_in[7];
    const float* dec_Wih  = (const float*)d_in[8];
    const float* dec_Whh  = (const float*)d_in[9];
    const float* dec_bih  = (const float*)d_in[10];
    const float* dec_bhh  = (const float*)d_in[11];
    const float* dec_init = (const float*)d_in[12];
    const float* lin_W    = (const float*)d_in[13];
    const float* lin_b    = (const float*)d_in[14];
    float* out = (float*)d_out;

    float *gx, *ctxg, *states, *hfin;
    int *didx, *bar;
    __nv_bfloat16 *pAh, *pAl, *pBh, *pBl, *weH, *weL, *wdH, *wdL;
    cudaGetSymbolAddress((void**)&gx, g_gx);
    cudaGetSymbolAddress((void**)&ctxg, g_ctxg);
    cudaGetSymbolAddress((void**)&states, g_states);
    cudaGetSymbolAddress((void**)&hfin, g_hfin);
    cudaGetSymbolAddress((void**)&didx, g_didx);
    cudaGetSymbolAddress((void**)&bar, g_bar);
    cudaGetSymbolAddress((void**)&pAh, g_Ah);
    cudaGetSymbolAddress((void**)&pAl, g_Al);
    cudaGetSymbolAddress((void**)&pBh, g_Bh);
    cudaGetSymbolAddress((void**)&pBl, g_Bl);
    cudaGetSymbolAddress((void**)&weH, g_WencH);
    cudaGetSymbolAddress((void**)&weL, g_WencL);
    cudaGetSymbolAddress((void**)&wdH, g_WdecH);
    cudaGetSymbolAddress((void**)&wdL, g_WdecL);

    const int hmma_smem = 2 * STAGE_B;
    cudaFuncSetAttribute(hmma_nt<512>,  cudaFuncAttributeMaxDynamicSharedMemorySize, hmma_smem);
    cudaFuncSetAttribute(hmma_nt<1024>, cudaFuncAttributeMaxDynamicSharedMemorySize, hmma_smem);
    cudaFuncSetAttribute(recur<false>, cudaFuncAttributeMaxDynamicSharedMemorySize, SMEM_REC);
    cudaFuncSetAttribute(recur<true>,  cudaFuncAttributeMaxDynamicSharedMemorySize, SMEM_REC);

    // ---- one-time weight conversions ----
    whh_split<<<dim3(NCTA, 48), 256>>>(enc_Whh, weH, weL);
    whh_split<<<dim3(NCTA, 48), 256>>>(dec_Whh, wdH, wdL);

    // ---- encoder input gates: gx = gather(enc_emb, x) @ enc_Wih^T + enc_bih ----
    split_stride<<<G_, 128>>>(enc_Wih, E_, pBh, pBl, E_);
    gather_split<<<MT_, 128>>>(enc_emb, x, pAh, pAl);
    hmma_nt<512><<<dim3(MT_ / 128, G_ / 128), 256, hmma_smem>>>(
        pAh, pAl, pBh, pBl, enc_bih, gx, G_);

    // ---- encoder recurrence (persistent) ----
    cudaMemsetAsync(bar, 0, sizeof(int));
    recur<false><<<NCTA, 256, SMEM_REC>>>(weH, weL, gx, enc_bhh, nullptr, nullptr);

    // ---- ctx gate contribution (fp32, tiny) ----
    gemm64_nt<<<G_ / 32, 128>>>(hfin, H_, dec_Wih + E_, DI_, ctxg, G_, H_);

    // ---- decoder input gates ----
    build_didx<<<MT_ / 256, 256>>>(labels);
    gather_split<<<MT_, 128>>>(dec_emb, didx, pAh, pAl);
    split_stride<<<G_, 128>>>(dec_Wih, DI_, pBh, pBl, E_);
    hmma_nt<512><<<dim3(MT_ / 128, G_ / 128), 256, hmma_smem>>>(
        pAh, pAl, pBh, pBl, dec_bih, gx, G_);

    // ---- decoder recurrence (persistent) ----
    cudaMemsetAsync(bar, 0, sizeof(int));
    recur<true><<<NCTA, 256, SMEM_REC>>>(wdH, wdL, gx, dec_bhh, ctxg, dec_init);

    // ---- logits ----
    split_bf16<<<(MT_ * H_ / 4 + 255) / 256, 256>>>(states, pAh, pAl, MT_ * H_ / 4);
    split_bf16<<<((int)((size_t)V_ * H_ / 4) + 255) / 256, 256>>>(lin_W, pBh, pBl, (int)((size_t)V_ * H_ / 4));
    hmma_nt<1024><<<dim3(MT_ / 128, V_ / 128), 256, hmma_smem>>>(
        pAh, pAl, pBh, pBl, lin_b, out, V_);
}

// round 6
// speedup vs baseline: 2.8118x; 1.1033x over previous
#include <cuda_runtime.h>
#include <cuda_bf16.h>
#include <cstdint>

#define B_   64
#define T_   64
#define V_   32000
#define E_   512
#define H_   1024
#define G_   (3 * H_)
#define DI_  (E_ + H_)
#define MT_  (B_ * T_)
#define JC   16
#define NCTA 64
#define RKC  64

// ---------------- scratch (device globals; no allocation) ----------------
__device__ float g_gx[MT_ * G_];
__device__ float g_ctxg[B_ * G_];
__device__ float g_hfin[B_ * H_];
__device__ int   g_didx[MT_];
__device__ int   g_bar;
__device__ __nv_bfloat16 g_hb[2][2][B_ * H_];
__device__ __nv_bfloat16 g_Ah[MT_ * H_];
__device__ __nv_bfloat16 g_Al[MT_ * H_];
__device__ __nv_bfloat16 g_Bh[(size_t)V_ * H_];
__device__ __nv_bfloat16 g_Bl[(size_t)V_ * H_];
__device__ __nv_bfloat16 g_WencH[NCTA * 48 * H_];
__device__ __nv_bfloat16 g_WencL[NCTA * 48 * H_];
__device__ __nv_bfloat16 g_WdecH[NCTA * 48 * H_];
__device__ __nv_bfloat16 g_WdecL[NCTA * 48 * H_];

// ================= base-ISA helpers =================
__device__ __forceinline__ uint32_t smem_u32(const void* p) {
    uint32_t a;
    asm("{ .reg .u64 t; cvta.to.shared.u64 t, %1; cvt.u32.u64 %0, t; }" : "=r"(a) : "l"(p));
    return a;
}
__device__ __forceinline__ void cpasync16(uint32_t saddr, const void* g) {
    asm volatile("cp.async.cg.shared.global [%0], [%1], 16;" :: "r"(saddr), "l"(g));
}
#define CP_COMMIT() asm volatile("cp.async.commit_group;" ::: "memory")
#define CP_WAIT1()  asm volatile("cp.async.wait_group 1;" ::: "memory")
#define CP_WAIT0()  asm volatile("cp.async.wait_group 0;" ::: "memory")
#define GBAR(id)    asm volatile("bar.sync %0, 256;" :: "r"(id) : "memory")

__device__ __forceinline__ void ldsm4(uint32_t* r, uint32_t addr) {
    asm volatile("ldmatrix.sync.aligned.m8n8.x4.shared.b16 {%0,%1,%2,%3}, [%4];"
                 : "=r"(r[0]), "=r"(r[1]), "=r"(r[2]), "=r"(r[3]) : "r"(addr));
}
__device__ __forceinline__ void ldsm2(uint32_t* r, uint32_t addr) {
    asm volatile("ldmatrix.sync.aligned.m8n8.x2.shared.b16 {%0,%1}, [%2];"
                 : "=r"(r[0]), "=r"(r[1]) : "r"(addr));
}
__device__ __forceinline__ void mma_bf16(float* d, const uint32_t* a, const uint32_t* b) {
    asm volatile(
        "mma.sync.aligned.m16n8k16.row.col.f32.bf16.bf16.f32 "
        "{%0,%1,%2,%3}, {%4,%5,%6,%7}, {%8,%9}, {%0,%1,%2,%3};"
        : "+f"(d[0]), "+f"(d[1]), "+f"(d[2]), "+f"(d[3])
        : "r"(a[0]), "r"(a[1]), "r"(a[2]), "r"(a[3]), "r"(b[0]), "r"(b[1]));
}

// ================= conversion kernels =================
__global__ __launch_bounds__(256) void split_bf16(
    const float* __restrict__ src, __nv_bfloat16* __restrict__ hi,
    __nv_bfloat16* __restrict__ lo, int n4)
{
    int i = blockIdx.x * 256 + threadIdx.x;
    if (i >= n4) return;
    float4 v = ((const float4*)src)[i];
    __nv_bfloat16 h0 = __float2bfloat16(v.x), h1 = __float2bfloat16(v.y);
    __nv_bfloat16 h2 = __float2bfloat16(v.z), h3 = __float2bfloat16(v.w);
    __nv_bfloat16 l0 = __float2bfloat16(v.x - __bfloat162float(h0));
    __nv_bfloat16 l1 = __float2bfloat16(v.y - __bfloat162float(h1));
    __nv_bfloat16 l2 = __float2bfloat16(v.z - __bfloat162float(h2));
    __nv_bfloat16 l3 = __float2bfloat16(v.w - __bfloat162float(h3));
    __nv_bfloat162* ph = (__nv_bfloat162*)hi;
    __nv_bfloat162* pl = (__nv_bfloat162*)lo;
    ph[2 * i]     = __nv_bfloat162(h0, h1);
    ph[2 * i + 1] = __nv_bfloat162(h2, h3);
    pl[2 * i]     = __nv_bfloat162(l0, l1);
    pl[2 * i + 1] = __nv_bfloat162(l2, l3);
}

__global__ __launch_bounds__(128) void gather_split(
    const float* __restrict__ emb, const int* __restrict__ idx,
    __nv_bfloat16* __restrict__ hi, __nv_bfloat16* __restrict__ lo)
{
    int m = blockIdx.x;
    const float* src = emb + (size_t)idx[m] * E_;
    int c = threadIdx.x;
    float4 v = ((const float4*)src)[c];
    __nv_bfloat16 h0 = __float2bfloat16(v.x), h1 = __float2bfloat16(v.y);
    __nv_bfloat16 h2 = __float2bfloat16(v.z), h3 = __float2bfloat16(v.w);
    __nv_bfloat16 l0 = __float2bfloat16(v.x - __bfloat162float(h0));
    __nv_bfloat16 l1 = __float2bfloat16(v.y - __bfloat162float(h1));
    __nv_bfloat16 l2 = __float2bfloat16(v.z - __bfloat162float(h2));
    __nv_bfloat16 l3 = __float2bfloat16(v.w - __bfloat162float(h3));
    size_t o = (size_t)m * E_ + c * 4;
    __nv_bfloat162* ph = (__nv_bfloat162*)(hi + o);
    __nv_bfloat162* pl = (__nv_bfloat162*)(lo + o);
    ph[0] = __nv_bfloat162(h0, h1); ph[1] = __nv_bfloat162(h2, h3);
    pl[0] = __nv_bfloat162(l0, l1); pl[1] = __nv_bfloat162(l2, l3);
}

__global__ __launch_bounds__(128) void split_stride(
    const float* __restrict__ src, int ld,
    __nv_bfloat16* __restrict__ hi, __nv_bfloat16* __restrict__ lo, int kd)
{
    int row = blockIdx.x;
    const float* s = src + (size_t)row * ld;
    for (int c = threadIdx.x; c < kd / 4; c += 128) {
        float4 v = ((const float4*)s)[c];
        __nv_bfloat16 h0 = __float2bfloat16(v.x), h1 = __float2bfloat16(v.y);
        __nv_bfloat16 h2 = __float2bfloat16(v.z), h3 = __float2bfloat16(v.w);
        __nv_bfloat16 l0 = __float2bfloat16(v.x - __bfloat162float(h0));
        __nv_bfloat16 l1 = __float2bfloat16(v.y - __bfloat162float(h1));
        __nv_bfloat16 l2 = __float2bfloat16(v.z - __bfloat162float(h2));
        __nv_bfloat16 l3 = __float2bfloat16(v.w - __bfloat162float(h3));
        size_t o = (size_t)row * kd + c * 4;
        __nv_bfloat162* ph = (__nv_bfloat162*)(hi + o);
        __nv_bfloat162* pl = (__nv_bfloat162*)(lo + o);
        ph[0] = __nv_bfloat162(h0, h1); ph[1] = __nv_bfloat162(h2, h3);
        pl[0] = __nv_bfloat162(l0, l1); pl[1] = __nv_bfloat162(l2, l3);
    }
}

__global__ __launch_bounds__(256) void whh_split(
    const float* __restrict__ W, __nv_bfloat16* __restrict__ hi,
    __nv_bfloat16* __restrict__ lo)
{
    int cta = blockIdx.x, l = blockIdx.y;
    int g = l >> 4, jj = l & 15;
    const float* s = W + (size_t)(g * H_ + cta * JC + jj) * H_;
    size_t drow = ((size_t)cta * 48 + l) * H_;
    int c = threadIdx.x;
    float4 v = ((const float4*)s)[c];
    __nv_bfloat16 h0 = __float2bfloat16(v.x), h1 = __float2bfloat16(v.y);
    __nv_bfloat16 h2 = __float2bfloat16(v.z), h3 = __float2bfloat16(v.w);
    __nv_bfloat16 l0 = __float2bfloat16(v.x - __bfloat162float(h0));
    __nv_bfloat16 l1 = __float2bfloat16(v.y - __bfloat162float(h1));
    __nv_bfloat16 l2 = __float2bfloat16(v.z - __bfloat162float(h2));
    __nv_bfloat16 l3 = __float2bfloat16(v.w - __bfloat162float(h3));
    __nv_bfloat162* ph = (__nv_bfloat162*)(hi + drow + c * 4);
    __nv_bfloat162* pl = (__nv_bfloat162*)(lo + drow + c * 4);
    ph[0] = __nv_bfloat162(h0, h1); ph[1] = __nv_bfloat162(h2, h3);
    pl[0] = __nv_bfloat162(l0, l1); pl[1] = __nv_bfloat162(l2, l3);
}

__global__ void build_didx(const int* __restrict__ labels) {
    int m = blockIdx.x * 256 + threadIdx.x;
    if (m < MT_) {
        int t = m & (T_ - 1);
        g_didx[m] = (t == 0) ? 1 : labels[m - 1];
    }
}

// ================= HMMA NT GEMM (bf16 3-term split) =================
#define KCH 32
#define TILE_B  (128 * 64)
#define OFF_AH  0
#define OFF_AL  (TILE_B)
#define OFF_BH  (2 * TILE_B)
#define OFF_BL  (3 * TILE_B)
#define STAGE_B (4 * TILE_B)

__device__ __forceinline__ uint32_t swz(int r, int c) {
    return (uint32_t)(r * 64 + ((c ^ ((r >> 1) & 3)) << 4));
}

template <int KD>
__global__ __launch_bounds__(256) void hmma_nt(
    const __nv_bfloat16* __restrict__ Ah, const __nv_bfloat16* __restrict__ Al,
    const __nv_bfloat16* __restrict__ Bh, const __nv_bfloat16* __restrict__ Bl,
    const float* __restrict__ bias, float* __restrict__ C, int ldc)
{
    constexpr int NST = KD / KCH;
    extern __shared__ char sm[];
    const uint32_t sb = smem_u32(sm);
    const int tid = threadIdx.x;
    const int lane = tid & 31;
    const int wid = tid >> 5;
    const int m0 = blockIdx.x * 128;
    const int n0 = blockIdx.y * 128;
    const int wm = wid >> 2;
    const int wn = wid & 3;

    const int r0 = tid >> 2, c0 = tid & 3;
    const int r1 = r0 + 64;
    const uint32_t so0 = swz(r0, c0);
    const uint32_t so1 = swz(r1, c0);
    const __nv_bfloat16* gAh0 = Ah + (size_t)(m0 + r0) * KD + c0 * 8;
    const __nv_bfloat16* gAh1 = Ah + (size_t)(m0 + r1) * KD + c0 * 8;
    const __nv_bfloat16* gAl0 = Al + (size_t)(m0 + r0) * KD + c0 * 8;
    const __nv_bfloat16* gAl1 = Al + (size_t)(m0 + r1) * KD + c0 * 8;
    const __nv_bfloat16* gBh0 = Bh + (size_t)(n0 + r0) * KD + c0 * 8;
    const __nv_bfloat16* gBh1 = Bh + (size_t)(n0 + r1) * KD + c0 * 8;
    const __nv_bfloat16* gBl0 = Bl + (size_t)(n0 + r0) * KD + c0 * 8;
    const __nv_bfloat16* gBl1 = Bl + (size_t)(n0 + r1) * KD + c0 * 8;

    int arow[4], axr[4];
#pragma unroll
    for (int mi = 0; mi < 4; mi++) {
        int r = wm * 64 + mi * 16 + (lane & 7) + ((lane >> 3) & 1) * 8;
        arow[mi] = r * 64;
        axr[mi] = (r >> 1) & 3;
    }
    const int acb = (lane >> 4);
    int brow[2], bxr[2];
#pragma unroll
    for (int nf2 = 0; nf2 < 2; nf2++) {
        int r = wn * 32 + nf2 * 16 + (lane & 7) + ((lane >> 4) & 1) * 8;
        brow[nf2] = r * 64;
        bxr[nf2] = (r >> 1) & 3;
    }
    const int bcb = ((lane >> 3) & 1);

    float acc[4][4][4];
#pragma unroll
    for (int mi = 0; mi < 4; mi++)
#pragma unroll
        for (int nf = 0; nf < 4; nf++)
#pragma unroll
            for (int q = 0; q < 4; q++) acc[mi][nf][q] = 0.f;

#define ISSUE(buf, kb) do { \
        uint32_t s_ = sb + (buf) * STAGE_B; \
        cpasync16(s_ + OFF_AH + so0, gAh0 + (kb)); cpasync16(s_ + OFF_AH + so1, gAh1 + (kb)); \
        cpasync16(s_ + OFF_AL + so0, gAl0 + (kb)); cpasync16(s_ + OFF_AL + so1, gAl1 + (kb)); \
        cpasync16(s_ + OFF_BH + so0, gBh0 + (kb)); cpasync16(s_ + OFF_BH + so1, gBh1 + (kb)); \
        cpasync16(s_ + OFF_BL + so0, gBl0 + (kb)); cpasync16(s_ + OFF_BL + so1, gBl1 + (kb)); \
    } while (0)

    ISSUE(0, 0);
    CP_COMMIT();
    ISSUE(1, KCH);
    CP_COMMIT();

    for (int st = 0; st < NST; st++) {
        CP_WAIT1();
        __syncthreads();
        const uint32_t base = sb + (st & 1) * STAGE_B;

#pragma unroll
        for (int s = 0; s < 2; s++) {
            uint32_t ah[4][4], al[4][4];
#pragma unroll
            for (int mi = 0; mi < 4; mi++) {
                uint32_t off = arow[mi] + ((((2 * s + acb)) ^ axr[mi]) << 4);
                ldsm4(ah[mi], base + OFF_AH + off);
                ldsm4(al[mi], base + OFF_AL + off);
            }
            uint32_t bhf[2][4], blf[2][4];
#pragma unroll
            for (int nf2 = 0; nf2 < 2; nf2++) {
                uint32_t off = brow[nf2] + ((((2 * s + bcb)) ^ bxr[nf2]) << 4);
                ldsm4(bhf[nf2], base + OFF_BH + off);
                ldsm4(blf[nf2], base + OFF_BL + off);
            }
#pragma unroll
            for (int mi = 0; mi < 4; mi++) {
#pragma unroll
                for (int nf = 0; nf < 4; nf++) {
                    const uint32_t* bp = &bhf[nf >> 1][(nf & 1) * 2];
                    const uint32_t* bq = &blf[nf >> 1][(nf & 1) * 2];
                    mma_bf16(acc[mi][nf], ah[mi], bp);
                    mma_bf16(acc[mi][nf], ah[mi], bq);
                    mma_bf16(acc[mi][nf], al[mi], bp);
                }
            }
        }
        __syncthreads();
        if (st + 2 < NST) ISSUE(st & 1, (st + 2) * KCH);
        CP_COMMIT();
    }
#undef ISSUE

    const int erow = m0 + wm * 64 + (lane >> 2);
    const int ecol0 = n0 + wn * 32 + (lane & 3) * 2;
#pragma unroll
    for (int mi = 0; mi < 4; mi++) {
#pragma unroll
        for (int nf = 0; nf < 4; nf++) {
            int col = ecol0 + nf * 8;
            float2 bv = *(const float2*)(bias + col);
            int row = erow + mi * 16;
            float2 o0 = make_float2(acc[mi][nf][0] + bv.x, acc[mi][nf][1] + bv.y);
            float2 o1 = make_float2(acc[mi][nf][2] + bv.x, acc[mi][nf][3] + bv.y);
            *(float2*)(C + (size_t)row * ldc + col) = o0;
            *(float2*)(C + (size_t)(row + 8) * ldc + col) = o1;
        }
    }
}

// ================= persistent fused GRU recurrence v2 =================
// 64 CTAs x 512 threads; two k-split warp groups (8 warps each), named barriers.
// Per step per group: gh_part[64x48] over K=512; gate sums both parts.
#define RST_B   28672                       // A 8K+8K | B 6K+6K
#define GRP_B   (2 * RST_B)                 // 57344 per group
#define SC_OFF  (2 * GRP_B)                 // 114688
#define HS_OFF  (SC_OFF + 2 * 64 * 52 * 4)  // 141312
#define BH_OFF  (HS_OFF + 1024 * 4)         // 145408
#define CTX_OFF (BH_OFF + 256)              // 145664
#define SGX_OFF (CTX_OFF + 64 * 48 * 4)     // 157952
#define SMEM_REC (SGX_OFF + 2 * 64 * 48 * 4)  // 182528

__device__ __forceinline__ uint32_t rswz(int r, int c) {
    return (uint32_t)(r * 128 + ((c ^ (r & 7)) << 4));
}

template <bool DEC>
__global__ __launch_bounds__(512) void recur(
    const __nv_bfloat16* __restrict__ Wh, const __nv_bfloat16* __restrict__ Wl,
    const float* __restrict__ gx, const float* __restrict__ bhh,
    const float* __restrict__ ctxg, const float* __restrict__ dec_init)
{
    extern __shared__ char sm[];
    const uint32_t sb = smem_u32(sm);
    float* sC   = (float*)(sm + SC_OFF);      // [2][64*52]
    float* h_s  = (float*)(sm + HS_OFF);
    float* bhhs = (float*)(sm + BH_OFF);
    float* sctx = (float*)(sm + CTX_OFF);
    float* sgx  = (float*)(sm + SGX_OFF);     // [2][64*48]

    const int tid  = threadIdx.x;
    const int lane = tid & 31;
    const int wid  = tid >> 5;
    const int g    = wid >> 3;                // k-split group
    const int gw   = wid & 7;
    const int gtid = tid & 255;
    const int cta  = blockIdx.x;
    const int j0   = cta * JC;

    const __nv_bfloat16* wbh = Wh + (size_t)cta * 48 * H_;
    const __nv_bfloat16* wbl = Wl + (size_t)cta * 48 * H_;

    const int wm = gw >> 1, wh = gw & 1;
    const int ar = wm * 16 + (lane & 15);
    const int aca = lane >> 4;
    const int br_ = lane & 7;
    const int bca = (lane >> 3) & 1;
    const uint32_t gbase = sb + g * GRP_B;

    // ---- init ----
    if (tid < 48) bhhs[tid] = bhh[(tid >> 4) * H_ + j0 + (tid & 15)];
#pragma unroll
    for (int it = 0; it < 2; it++) {
        int item = tid + it * 512;
        int b = item >> 4, jj = item & 15;
        float h0 = DEC ? dec_init[j0 + jj] : 0.f;
        h_s[item] = h0;
        __nv_bfloat16 hh = __float2bfloat16(h0);
        __nv_bfloat16 hl = __float2bfloat16(h0 - __bfloat162float(hh));
        g_hb[0][0][b * H_ + j0 + jj] = hh;
        g_hb[0][1][b * H_ + j0 + jj] = hl;
    }
    // prologue prefetch: gx(0) and (DEC) ctxg slice
#pragma unroll
    for (int i = 0; i < 2; i++) {
        int v = tid + i * 512;
        if (v < 768) {
            int b = v / 12, rem = v - b * 12, q = rem >> 2, sg = rem & 3;
            uint32_t doff = (uint32_t)(b * 48 + q * 16 + sg * 4) * 4;
            cpasync16(sb + SGX_OFF + doff, gx + (size_t)(b * T_) * G_ + q * H_ + j0 + sg * 4);
            if (DEC)
                cpasync16(sb + CTX_OFF + doff, ctxg + (size_t)b * G_ + q * H_ + j0 + sg * 4);
        }
    }
    CP_COMMIT();
    __syncthreads();
    if (tid == 0) {
        __threadfence();
        atomicAdd(&g_bar, 1);
        volatile int* vb = &g_bar;
        while (*vb < NCTA) __nanosleep(64);
        __threadfence();
    }
    __syncthreads();

    for (int t = 0; t < T_; t++) {
        // A source for this step
        const __nv_bfloat16 *pAh, *pAl;
        size_t astr;
        if (DEC) {
            if (t == 0) { pAh = g_hb[0][0]; pAl = g_hb[0][1]; astr = H_; }
            else {
                pAh = g_Ah + (size_t)(t - 1) * H_;
                pAl = g_Al + (size_t)(t - 1) * H_;
                astr = (size_t)T_ * H_;
            }
        } else {
            pAh = g_hb[t & 1][0]; pAl = g_hb[t & 1][1]; astr = H_;
        }

        auto rissue = [&](int buf, int chunk) {
            uint32_t s_ = gbase + (uint32_t)buf * RST_B;
            const __nv_bfloat16* ah = pAh + (size_t)chunk * RKC;
            const __nv_bfloat16* al = pAl + (size_t)chunk * RKC;
            const __nv_bfloat16* bh = wbh + (size_t)chunk * RKC;
            const __nv_bfloat16* bl = wbl + (size_t)chunk * RKC;
#pragma unroll
            for (int i_ = 0; i_ < 2; i_++) {
                int v_ = gtid + i_ * 256;
                int r_ = v_ >> 3, c_ = v_ & 7;
                uint32_t so_ = rswz(r_, c_);
                cpasync16(s_ + so_,          ah + (size_t)r_ * astr + c_ * 8);
                cpasync16(s_ + 8192u + so_,  al + (size_t)r_ * astr + c_ * 8);
                if (v_ < 384) {
                    cpasync16(s_ + 16384u + so_, bh + (size_t)r_ * H_ + c_ * 8);
                    cpasync16(s_ + 22528u + so_, bl + (size_t)r_ * H_ + c_ * 8);
                }
            }
        };

        float acc[3][4];
#pragma unroll
        for (int nt = 0; nt < 3; nt++)
#pragma unroll
            for (int q = 0; q < 4; q++) acc[nt][q] = 0.f;

        const int c0 = g * 8;
        rissue(0, c0);     CP_COMMIT();
        rissue(1, c0 + 1); CP_COMMIT();

#pragma unroll 1
        for (int kc = 0; kc < 8; kc++) {
            CP_WAIT1();
            GBAR(1 + g);
            const uint32_t base = gbase + (uint32_t)(kc & 1) * RST_B;
#pragma unroll
            for (int s = 0; s < 4; s++) {
                uint32_t aH[4], aL[4];
                uint32_t offA = (uint32_t)(ar * 128 + (((2 * s + aca) ^ (ar & 7)) << 4));
                ldsm4(aH, base + offA);
                ldsm4(aL, base + 8192u + offA);
#pragma unroll
                for (int nt = 0; nt < 3; nt++) {
                    int rb0 = wh * 24 + nt * 8 + br_;
                    uint32_t offB = (uint32_t)(rb0 * 128 + (((2 * s + bca) ^ (rb0 & 7)) << 4));
                    uint32_t bH[2], bL[2];
                    ldsm2(bH, base + 16384u + offB);
                    ldsm2(bL, base + 22528u + offB);
                    mma_bf16(acc[nt], aH, bH);
                    mma_bf16(acc[nt], aH, bL);
                    mma_bf16(acc[nt], aL, bH);
                }
            }
            GBAR(1 + g);
            if (kc + 2 < 8) rissue(kc & 1, c0 + kc + 2);
            CP_COMMIT();
        }

        // prefetch gx(t+1)
        if (t + 1 < T_) {
#pragma unroll
            for (int i = 0; i < 2; i++) {
                int v = tid + i * 512;
                if (v < 768) {
                    int b = v / 12, rem = v - b * 12, q = rem >> 2, sg = rem & 3;
                    uint32_t doff = (uint32_t)(((t + 1) & 1) * 3072 + b * 48 + q * 16 + sg * 4) * 4;
                    cpasync16(sb + SGX_OFF + doff,
                              gx + (size_t)(b * T_ + t + 1) * G_ + q * H_ + j0 + sg * 4);
                }
            }
            CP_COMMIT();
        }

        // stage partial gh to smem
        {
            float* sCg = sC + g * (64 * 52);
            int crow = wm * 16 + (lane >> 2);
            int ccol = wh * 24 + (lane & 3) * 2;
#pragma unroll
            for (int nt = 0; nt < 3; nt++) {
                int cc = ccol + nt * 8;
                *(float2*)&sCg[crow * 52 + cc]       = make_float2(acc[nt][0], acc[nt][1]);
                *(float2*)&sCg[(crow + 8) * 52 + cc] = make_float2(acc[nt][2], acc[nt][3]);
            }
        }
        CP_WAIT0();
        __syncthreads();

        // gate
        const float* sgxt = sgx + (t & 1) * 3072;
#pragma unroll
        for (int it = 0; it < 2; it++) {
            int item = tid + it * 512;
            int b = item >> 4, jj = item & 15;
            float ghr = sC[b * 52 + jj]      + sC[64 * 52 + b * 52 + jj]      + bhhs[jj];
            float ghz = sC[b * 52 + 16 + jj] + sC[64 * 52 + b * 52 + 16 + jj] + bhhs[16 + jj];
            float ghn = sC[b * 52 + 32 + jj] + sC[64 * 52 + b * 52 + 32 + jj] + bhhs[32 + jj];
            float xr = sgxt[b * 48 + jj];
            float xz = sgxt[b * 48 + 16 + jj];
            float xn = sgxt[b * 48 + 32 + jj];
            if (DEC) {
                xr += sctx[b * 48 + jj];
                xz += sctx[b * 48 + 16 + jj];
                xn += sctx[b * 48 + 32 + jj];
            }
            float r = 1.f / (1.f + expf(-(xr + ghr)));
            float z = 1.f / (1.f + expf(-(xz + ghz)));
            float n = tanhf(xn + r * ghn);
            float h2 = (1.f - z) * n + z * h_s[item];
            h_s[item] = h2;
            __nv_bfloat16 hh = __float2bfloat16(h2);
            __nv_bfloat16 hl = __float2bfloat16(h2 - __bfloat162float(hh));
            if (DEC) {
                size_t row = (size_t)(b * T_ + t) * H_ + j0 + jj;
                g_Ah[row] = hh;
                g_Al[row] = hl;
            } else {
                int gc = b * H_ + j0 + jj;
                g_hb[(t & 1) ^ 1][0][gc] = hh;
                g_hb[(t & 1) ^ 1][1][gc] = hl;
                if (t == T_ - 1) g_hfin[gc] = h2;
            }
        }
        __syncthreads();
        if (tid == 0) {
            __threadfence();
            atomicAdd(&g_bar, 1);
            int target = NCTA * (t + 2);
            volatile int* vb = &g_bar;
            while (*vb < target) __nanosleep(64);
            __threadfence();
        }
        __syncthreads();
    }
}

// ---------------- small fp32 NT GEMM for ctxg ----------------
__global__ __launch_bounds__(128) void gemm64_nt(
    const float* __restrict__ A, int lda,
    const float* __restrict__ Bm, int ldb,
    float* __restrict__ C, int ldc, int klen)
{
    __shared__ float As[16][64];
    __shared__ float Bs[16][32];

    const int tid = threadIdx.x;
    const int tx = tid & 7;
    const int ty = tid >> 3;
    const int n0 = blockIdx.x * 32;

    const int am0 = tid >> 2;
    const int am1 = am0 + 32;
    const int ak  = (tid & 3) * 4;

    const float* Ar0 = A + (size_t)am0 * lda;
    const float* Ar1 = A + (size_t)am1 * lda;
    const float* Br  = Bm + (size_t)(n0 + am0) * ldb;

    float acc[4][4];
#pragma unroll
    for (int i = 0; i < 4; i++)
#pragma unroll
        for (int j = 0; j < 4; j++) acc[i][j] = 0.f;

    for (int k0 = 0; k0 < klen; k0 += 16) {
        float4 a0 = *(const float4*)(Ar0 + k0 + ak);
        float4 a1 = *(const float4*)(Ar1 + k0 + ak);
        float4 b  = *(const float4*)(Br  + k0 + ak);

        __syncthreads();
        As[ak + 0][am0] = a0.x; As[ak + 1][am0] = a0.y; As[ak + 2][am0] = a0.z; As[ak + 3][am0] = a0.w;
        As[ak + 0][am1] = a1.x; As[ak + 1][am1] = a1.y; As[ak + 2][am1] = a1.z; As[ak + 3][am1] = a1.w;
        Bs[ak + 0][am0] = b.x;  Bs[ak + 1][am0] = b.y;  Bs[ak + 2][am0] = b.z;  Bs[ak + 3][am0] = b.w;
        __syncthreads();

#pragma unroll
        for (int kk = 0; kk < 16; kk++) {
            float4 av = *(const float4*)&As[kk][ty * 4];
            float4 bv = *(const float4*)&Bs[kk][tx * 4];
            float a[4] = {av.x, av.y, av.z, av.w};
            float b4[4] = {bv.x, bv.y, bv.z, bv.w};
#pragma unroll
            for (int i = 0; i < 4; i++)
#pragma unroll
                for (int j = 0; j < 4; j++) acc[i][j] += a[i] * b4[j];
        }
    }

#pragma unroll
    for (int i = 0; i < 4; i++) {
        int m = ty * 4 + i;
        float* crow = C + (size_t)m * ldc + n0 + tx * 4;
        *(float4*)crow = make_float4(acc[i][0], acc[i][1], acc[i][2], acc[i][3]);
    }
}

// ---------------- launch ----------------
extern "C" void kernel_launch(void* const* d_in, const int* in_sizes, int n_in,
                              void* d_out, int out_size)
{
    const int*   x        = (const int*)d_in[0];
    const int*   labels   = (const int*)d_in[1];
    const float* enc_emb  = (const float*)d_in[2];
    const float* enc_Wih  = (const float*)d_in[3];
    const float* enc_Whh  = (const float*)d_in[4];
    const float* enc_bih  = (const float*)d_in[5];
    const float* enc_bhh  = (const float*)d_in[6];
    const float* dec_emb  = (const float*)d_in[7];
    const float* dec_Wih  = (const float*)d_in[8];
    const float* dec_Whh  = (const float*)d_in[9];
    const float* dec_bih  = (const float*)d_in[10];
    const float* dec_bhh  = (const float*)d_in[11];
    const float* dec_init = (const float*)d_in[12];
    const float* lin_W    = (const float*)d_in[13];
    const float* lin_b    = (const float*)d_in[14];
    float* out = (float*)d_out;

    float *gx, *ctxg, *hfin;
    int *didx, *bar;
    __nv_bfloat16 *pAh, *pAl, *pBh, *pBl, *weH, *weL, *wdH, *wdL;
    cudaGetSymbolAddress((void**)&gx, g_gx);
    cudaGetSymbolAddress((void**)&ctxg, g_ctxg);
    cudaGetSymbolAddress((void**)&hfin, g_hfin);
    cudaGetSymbolAddress((void**)&didx, g_didx);
    cudaGetSymbolAddress((void**)&bar, g_bar);
    cudaGetSymbolAddress((void**)&pAh, g_Ah);
    cudaGetSymbolAddress((void**)&pAl, g_Al);
    cudaGetSymbolAddress((void**)&pBh, g_Bh);
    cudaGetSymbolAddress((void**)&pBl, g_Bl);
    cudaGetSymbolAddress((void**)&weH, g_WencH);
    cudaGetSymbolAddress((void**)&weL, g_WencL);
    cudaGetSymbolAddress((void**)&wdH, g_WdecH);
    cudaGetSymbolAddress((void**)&wdL, g_WdecL);

    const int hmma_smem = 2 * STAGE_B;
    cudaFuncSetAttribute(hmma_nt<512>,  cudaFuncAttributeMaxDynamicSharedMemorySize, hmma_smem);
    cudaFuncSetAttribute(hmma_nt<1024>, cudaFuncAttributeMaxDynamicSharedMemorySize, hmma_smem);
    cudaFuncSetAttribute(recur<false>, cudaFuncAttributeMaxDynamicSharedMemorySize, SMEM_REC);
    cudaFuncSetAttribute(recur<true>,  cudaFuncAttributeMaxDynamicSharedMemorySize, SMEM_REC);

    // one-time weight conversions
    whh_split<<<dim3(NCTA, 48), 256>>>(enc_Whh, weH, weL);
    whh_split<<<dim3(NCTA, 48), 256>>>(dec_Whh, wdH, wdL);

    // encoder input gates
    split_stride<<<G_, 128>>>(enc_Wih, E_, pBh, pBl, E_);
    gather_split<<<MT_, 128>>>(enc_emb, x, pAh, pAl);
    hmma_nt<512><<<dim3(MT_ / 128, G_ / 128), 256, hmma_smem>>>(
        pAh, pAl, pBh, pBl, enc_bih, gx, G_);

    // encoder recurrence
    cudaMemsetAsync(bar, 0, sizeof(int));
    recur<false><<<NCTA, 512, SMEM_REC>>>(weH, weL, gx, enc_bhh, nullptr, nullptr);

    // ctx gate contribution
    gemm64_nt<<<G_ / 32, 128>>>(hfin, H_, dec_Wih + E_, DI_, ctxg, G_, H_);

    // decoder input gates
    build_didx<<<MT_ / 256, 256>>>(labels);
    gather_split<<<MT_, 128>>>(dec_emb, didx, pAh, pAl);
    split_stride<<<G_, 128>>>(dec_Wih, DI_, pBh, pBl, E_);
    hmma_nt<512><<<dim3(MT_ / 128, G_ / 128), 256, hmma_smem>>>(
        pAh, pAl, pBh, pBl, dec_bih, gx, G_);

    // decoder recurrence (writes bf16 hi/lo states directly into g_Ah/g_Al)
    cudaMemsetAsync(bar, 0, sizeof(int));
    recur<true><<<NCTA, 512, SMEM_REC>>>(wdH, wdL, gx, dec_bhh, ctxg, dec_init);

    // logits
    split_bf16<<<((int)((size_t)V_ * H_ / 4) + 255) / 256, 256>>>(
        lin_W, pBh, pBl, (int)((size_t)V_ * H_ / 4));
    hmma_nt<1024><<<dim3(MT_ / 128, V_ / 128), 256, hmma_smem>>>(
        pAh, pAl, pBh, pBl, lin_b, out, V_);
}

// round 7
// speedup vs baseline: 3.3030x; 1.1747x over previous
#include <cuda_runtime.h>
#include <cuda_bf16.h>
#include <cstdint>

#define B_   64
#define T_   64
#define V_   32000
#define E_   512
#define H_   1024
#define G_   (3 * H_)
#define DI_  (E_ + H_)
#define MT_  (B_ * T_)
#define JC     8            // h-columns per CTA
#define NR     24           // gate rows per CTA (3*JC)
#define NCTA_R 128
#define RKC    64

// ---------------- scratch (device globals; no allocation) ----------------
__device__ float g_gx[MT_ * G_];
__device__ float g_ctxg[B_ * G_];
__device__ float g_hfin[B_ * H_];
__device__ int   g_didx[MT_];
__device__ int   g_bar;
__device__ __nv_bfloat16 g_hb[2][2][B_ * H_];
__device__ __nv_bfloat16 g_Ah[MT_ * H_];
__device__ __nv_bfloat16 g_Al[MT_ * H_];
__device__ __nv_bfloat16 g_Bh[(size_t)V_ * H_];
__device__ __nv_bfloat16 g_Bl[(size_t)V_ * H_];
__device__ __nv_bfloat16 g_WencH[NCTA_R * NR * H_];
__device__ __nv_bfloat16 g_WencL[NCTA_R * NR * H_];
__device__ __nv_bfloat16 g_WdecH[NCTA_R * NR * H_];
__device__ __nv_bfloat16 g_WdecL[NCTA_R * NR * H_];

// ================= base-ISA helpers =================
__device__ __forceinline__ uint32_t smem_u32(const void* p) {
    uint32_t a;
    asm("{ .reg .u64 t; cvta.to.shared.u64 t, %1; cvt.u32.u64 %0, t; }" : "=r"(a) : "l"(p));
    return a;
}
__device__ __forceinline__ void cpasync16(uint32_t saddr, const void* g) {
    asm volatile("cp.async.cg.shared.global [%0], [%1], 16;" :: "r"(saddr), "l"(g));
}
#define CP_COMMIT() asm volatile("cp.async.commit_group;" ::: "memory")
#define CP_WAIT1()  asm volatile("cp.async.wait_group 1;" ::: "memory")
#define CP_WAIT0()  asm volatile("cp.async.wait_group 0;" ::: "memory")
#define GBAR(id)    asm volatile("bar.sync %0, 256;" :: "r"(id) : "memory")

__device__ __forceinline__ void ldsm4(uint32_t* r, uint32_t addr) {
    asm volatile("ldmatrix.sync.aligned.m8n8.x4.shared.b16 {%0,%1,%2,%3}, [%4];"
                 : "=r"(r[0]), "=r"(r[1]), "=r"(r[2]), "=r"(r[3]) : "r"(addr));
}
__device__ __forceinline__ void ldsm2(uint32_t* r, uint32_t addr) {
    asm volatile("ldmatrix.sync.aligned.m8n8.x2.shared.b16 {%0,%1}, [%2];"
                 : "=r"(r[0]), "=r"(r[1]) : "r"(addr));
}
__device__ __forceinline__ void mma_bf16(float* d, const uint32_t* a, const uint32_t* b) {
    asm volatile(
        "mma.sync.aligned.m16n8k16.row.col.f32.bf16.bf16.f32 "
        "{%0,%1,%2,%3}, {%4,%5,%6,%7}, {%8,%9}, {%0,%1,%2,%3};"
        : "+f"(d[0]), "+f"(d[1]), "+f"(d[2]), "+f"(d[3])
        : "r"(a[0]), "r"(a[1]), "r"(a[2]), "r"(a[3]), "r"(b[0]), "r"(b[1]));
}

// ================= conversion kernels =================
__global__ __launch_bounds__(256) void split_bf16(
    const float* __restrict__ src, __nv_bfloat16* __restrict__ hi,
    __nv_bfloat16* __restrict__ lo, int n4)
{
    int i = blockIdx.x * 256 + threadIdx.x;
    if (i >= n4) return;
    float4 v = ((const float4*)src)[i];
    __nv_bfloat16 h0 = __float2bfloat16(v.x), h1 = __float2bfloat16(v.y);
    __nv_bfloat16 h2 = __float2bfloat16(v.z), h3 = __float2bfloat16(v.w);
    __nv_bfloat16 l0 = __float2bfloat16(v.x - __bfloat162float(h0));
    __nv_bfloat16 l1 = __float2bfloat16(v.y - __bfloat162float(h1));
    __nv_bfloat16 l2 = __float2bfloat16(v.z - __bfloat162float(h2));
    __nv_bfloat16 l3 = __float2bfloat16(v.w - __bfloat162float(h3));
    __nv_bfloat162* ph = (__nv_bfloat162*)hi;
    __nv_bfloat162* pl = (__nv_bfloat162*)lo;
    ph[2 * i]     = __nv_bfloat162(h0, h1);
    ph[2 * i + 1] = __nv_bfloat162(h2, h3);
    pl[2 * i]     = __nv_bfloat162(l0, l1);
    pl[2 * i + 1] = __nv_bfloat162(l2, l3);
}

__global__ __launch_bounds__(128) void gather_split(
    const float* __restrict__ emb, const int* __restrict__ idx,
    __nv_bfloat16* __restrict__ hi, __nv_bfloat16* __restrict__ lo)
{
    int m = blockIdx.x;
    const float* src = emb + (size_t)idx[m] * E_;
    int c = threadIdx.x;
    float4 v = ((const float4*)src)[c];
    __nv_bfloat16 h0 = __float2bfloat16(v.x), h1 = __float2bfloat16(v.y);
    __nv_bfloat16 h2 = __float2bfloat16(v.z), h3 = __float2bfloat16(v.w);
    __nv_bfloat16 l0 = __float2bfloat16(v.x - __bfloat162float(h0));
    __nv_bfloat16 l1 = __float2bfloat16(v.y - __bfloat162float(h1));
    __nv_bfloat16 l2 = __float2bfloat16(v.z - __bfloat162float(h2));
    __nv_bfloat16 l3 = __float2bfloat16(v.w - __bfloat162float(h3));
    size_t o = (size_t)m * E_ + c * 4;
    __nv_bfloat162* ph = (__nv_bfloat162*)(hi + o);
    __nv_bfloat162* pl = (__nv_bfloat162*)(lo + o);
    ph[0] = __nv_bfloat162(h0, h1); ph[1] = __nv_bfloat162(h2, h3);
    pl[0] = __nv_bfloat162(l0, l1); pl[1] = __nv_bfloat162(l2, l3);
}

__global__ __launch_bounds__(128) void split_stride(
    const float* __restrict__ src, int ld,
    __nv_bfloat16* __restrict__ hi, __nv_bfloat16* __restrict__ lo, int kd)
{
    int row = blockIdx.x;
    const float* s = src + (size_t)row * ld;
    for (int c = threadIdx.x; c < kd / 4; c += 128) {
        float4 v = ((const float4*)s)[c];
        __nv_bfloat16 h0 = __float2bfloat16(v.x), h1 = __float2bfloat16(v.y);
        __nv_bfloat16 h2 = __float2bfloat16(v.z), h3 = __float2bfloat16(v.w);
        __nv_bfloat16 l0 = __float2bfloat16(v.x - __bfloat162float(h0));
        __nv_bfloat16 l1 = __float2bfloat16(v.y - __bfloat162float(h1));
        __nv_bfloat16 l2 = __float2bfloat16(v.z - __bfloat162float(h2));
        __nv_bfloat16 l3 = __float2bfloat16(v.w - __bfloat162float(h3));
        size_t o = (size_t)row * kd + c * 4;
        __nv_bfloat162* ph = (__nv_bfloat162*)(hi + o);
        __nv_bfloat162* pl = (__nv_bfloat162*)(lo + o);
        ph[0] = __nv_bfloat162(h0, h1); ph[1] = __nv_bfloat162(h2, h3);
        pl[0] = __nv_bfloat162(l0, l1); pl[1] = __nv_bfloat162(l2, l3);
    }
}

// rearrange+split Whh for JC=8: dst row = cta*NR + l, l = gate*8+jj <- src row gate*H + cta*8 + jj
__global__ __launch_bounds__(256) void whh_split(
    const float* __restrict__ W, __nv_bfloat16* __restrict__ hi,
    __nv_bfloat16* __restrict__ lo)
{
    int cta = blockIdx.x, l = blockIdx.y;
    int g = l >> 3, jj = l & 7;
    const float* s = W + (size_t)(g * H_ + cta * JC + jj) * H_;
    size_t drow = ((size_t)cta * NR + l) * H_;
    int c = threadIdx.x;
    float4 v = ((const float4*)s)[c];
    __nv_bfloat16 h0 = __float2bfloat16(v.x), h1 = __float2bfloat16(v.y);
    __nv_bfloat16 h2 = __float2bfloat16(v.z), h3 = __float2bfloat16(v.w);
    __nv_bfloat16 l0 = __float2bfloat16(v.x - __bfloat162float(h0));
    __nv_bfloat16 l1 = __float2bfloat16(v.y - __bfloat162float(h1));
    __nv_bfloat16 l2 = __float2bfloat16(v.z - __bfloat162float(h2));
    __nv_bfloat16 l3 = __float2bfloat16(v.w - __bfloat162float(h3));
    __nv_bfloat162* ph = (__nv_bfloat162*)(hi + drow + c * 4);
    __nv_bfloat162* pl = (__nv_bfloat162*)(lo + drow + c * 4);
    ph[0] = __nv_bfloat162(h0, h1); ph[1] = __nv_bfloat162(h2, h3);
    pl[0] = __nv_bfloat162(l0, l1); pl[1] = __nv_bfloat162(l2, l3);
}

__global__ void build_didx(const int* __restrict__ labels) {
    int m = blockIdx.x * 256 + threadIdx.x;
    if (m < MT_) {
        int t = m & (T_ - 1);
        g_didx[m] = (t == 0) ? 1 : labels[m - 1];
    }
}

// ================= HMMA NT GEMM (bf16 3-term split) =================
#define KCH 32
#define TILE_B  (128 * 64)
#define OFF_AH  0
#define OFF_AL  (TILE_B)
#define OFF_BH  (2 * TILE_B)
#define OFF_BL  (3 * TILE_B)
#define STAGE_B (4 * TILE_B)

__device__ __forceinline__ uint32_t swz(int r, int c) {
    return (uint32_t)(r * 64 + ((c ^ ((r >> 1) & 3)) << 4));
}

template <int KD>
__global__ __launch_bounds__(256) void hmma_nt(
    const __nv_bfloat16* __restrict__ Ah, const __nv_bfloat16* __restrict__ Al,
    const __nv_bfloat16* __restrict__ Bh, const __nv_bfloat16* __restrict__ Bl,
    const float* __restrict__ bias, float* __restrict__ C, int ldc)
{
    constexpr int NST = KD / KCH;
    extern __shared__ char sm[];
    const uint32_t sb = smem_u32(sm);
    const int tid = threadIdx.x;
    const int lane = tid & 31;
    const int wid = tid >> 5;
    const int m0 = blockIdx.x * 128;
    const int n0 = blockIdx.y * 128;
    const int wm = wid >> 2;
    const int wn = wid & 3;

    const int r0 = tid >> 2, c0 = tid & 3;
    const int r1 = r0 + 64;
    const uint32_t so0 = swz(r0, c0);
    const uint32_t so1 = swz(r1, c0);
    const __nv_bfloat16* gAh0 = Ah + (size_t)(m0 + r0) * KD + c0 * 8;
    const __nv_bfloat16* gAh1 = Ah + (size_t)(m0 + r1) * KD + c0 * 8;
    const __nv_bfloat16* gAl0 = Al + (size_t)(m0 + r0) * KD + c0 * 8;
    const __nv_bfloat16* gAl1 = Al + (size_t)(m0 + r1) * KD + c0 * 8;
    const __nv_bfloat16* gBh0 = Bh + (size_t)(n0 + r0) * KD + c0 * 8;
    const __nv_bfloat16* gBh1 = Bh + (size_t)(n0 + r1) * KD + c0 * 8;
    const __nv_bfloat16* gBl0 = Bl + (size_t)(n0 + r0) * KD + c0 * 8;
    const __nv_bfloat16* gBl1 = Bl + (size_t)(n0 + r1) * KD + c0 * 8;

    int arow[4], axr[4];
#pragma unroll
    for (int mi = 0; mi < 4; mi++) {
        int r = wm * 64 + mi * 16 + (lane & 7) + ((lane >> 3) & 1) * 8;
        arow[mi] = r * 64;
        axr[mi] = (r >> 1) & 3;
    }
    const int acb = (lane >> 4);
    int brow[2], bxr[2];
#pragma unroll
    for (int nf2 = 0; nf2 < 2; nf2++) {
        int r = wn * 32 + nf2 * 16 + (lane & 7) + ((lane >> 4) & 1) * 8;
        brow[nf2] = r * 64;
        bxr[nf2] = (r >> 1) & 3;
    }
    const int bcb = ((lane >> 3) & 1);

    float acc[4][4][4];
#pragma unroll
    for (int mi = 0; mi < 4; mi++)
#pragma unroll
        for (int nf = 0; nf < 4; nf++)
#pragma unroll
            for (int q = 0; q < 4; q++) acc[mi][nf][q] = 0.f;

#define ISSUE(buf, kb) do { \
        uint32_t s_ = sb + (buf) * STAGE_B; \
        cpasync16(s_ + OFF_AH + so0, gAh0 + (kb)); cpasync16(s_ + OFF_AH + so1, gAh1 + (kb)); \
        cpasync16(s_ + OFF_AL + so0, gAl0 + (kb)); cpasync16(s_ + OFF_AL + so1, gAl1 + (kb)); \
        cpasync16(s_ + OFF_BH + so0, gBh0 + (kb)); cpasync16(s_ + OFF_BH + so1, gBh1 + (kb)); \
        cpasync16(s_ + OFF_BL + so0, gBl0 + (kb)); cpasync16(s_ + OFF_BL + so1, gBl1 + (kb)); \
    } while (0)

    ISSUE(0, 0);
    CP_COMMIT();
    ISSUE(1, KCH);
    CP_COMMIT();

    for (int st = 0; st < NST; st++) {
        CP_WAIT1();
        __syncthreads();
        const uint32_t base = sb + (st & 1) * STAGE_B;

#pragma unroll
        for (int s = 0; s < 2; s++) {
            uint32_t ah[4][4], al[4][4];
#pragma unroll
            for (int mi = 0; mi < 4; mi++) {
                uint32_t off = arow[mi] + ((((2 * s + acb)) ^ axr[mi]) << 4);
                ldsm4(ah[mi], base + OFF_AH + off);
                ldsm4(al[mi], base + OFF_AL + off);
            }
            uint32_t bhf[2][4], blf[2][4];
#pragma unroll
            for (int nf2 = 0; nf2 < 2; nf2++) {
                uint32_t off = brow[nf2] + ((((2 * s + bcb)) ^ bxr[nf2]) << 4);
                ldsm4(bhf[nf2], base + OFF_BH + off);
                ldsm4(blf[nf2], base + OFF_BL + off);
            }
#pragma unroll
            for (int mi = 0; mi < 4; mi++) {
#pragma unroll
                for (int nf = 0; nf < 4; nf++) {
                    const uint32_t* bp = &bhf[nf >> 1][(nf & 1) * 2];
                    const uint32_t* bq = &blf[nf >> 1][(nf & 1) * 2];
                    mma_bf16(acc[mi][nf], ah[mi], bp);
                    mma_bf16(acc[mi][nf], ah[mi], bq);
                    mma_bf16(acc[mi][nf], al[mi], bp);
                }
            }
        }
        __syncthreads();
        if (st + 2 < NST) ISSUE(st & 1, (st + 2) * KCH);
        CP_COMMIT();
    }
#undef ISSUE

    const int erow = m0 + wm * 64 + (lane >> 2);
    const int ecol0 = n0 + wn * 32 + (lane & 3) * 2;
#pragma unroll
    for (int mi = 0; mi < 4; mi++) {
#pragma unroll
        for (int nf = 0; nf < 4; nf++) {
            int col = ecol0 + nf * 8;
            float2 bv = *(const float2*)(bias + col);
            int row = erow + mi * 16;
            float2 o0 = make_float2(acc[mi][nf][0] + bv.x, acc[mi][nf][1] + bv.y);
            float2 o1 = make_float2(acc[mi][nf][2] + bv.x, acc[mi][nf][3] + bv.y);
            *(float2*)(C + (size_t)row * ldc + col) = o0;
            *(float2*)(C + (size_t)(row + 8) * ldc + col) = o1;
        }
    }
}

// ================= persistent fused GRU recurrence v3 =================
// 128 CTAs x 512 threads, JC=8 (24 gate rows/CTA). Weights smem-RESIDENT.
// 16 warps = 2 outer k-groups (A buffers) x 4 m-warps x 2 inner s-splits.
// Per step: 4 k-partials of gh[64x24], reduced in the gate.
#define WH_OFF  0
#define WL_OFF  49152
#define AB_OFF  98304          // + g*32768 + stage*16384 ; lo at +8192
#define SC_OFF  163840         // 4 partials x 64x28 f32 (7168 B each)
#define HS_OFF  192512         // 512 f32
#define BHB_OFF 194560         // 24 f32
#define CTX_OFF 194656         // 64x24 f32
#define SGX_OFF 200800         // 2 x 64x24 f32
#define SMEM_REC 213088

__device__ __forceinline__ uint32_t rswz(int r, int c) {
    return (uint32_t)(r * 128 + ((c ^ (r & 7)) << 4));
}

template <bool DEC>
__global__ __launch_bounds__(512) void recur(
    const __nv_bfloat16* __restrict__ Wh, const __nv_bfloat16* __restrict__ Wl,
    const float* __restrict__ gx, const float* __restrict__ bhh,
    const float* __restrict__ ctxg, const float* __restrict__ dec_init)
{
    extern __shared__ char sm[];
    const uint32_t sb = smem_u32(sm);
    float* sC   = (float*)(sm + SC_OFF);
    float* h_s  = (float*)(sm + HS_OFF);
    float* bhhs = (float*)(sm + BHB_OFF);
    float* sctx = (float*)(sm + CTX_OFF);
    float* sgx  = (float*)(sm + SGX_OFF);

    const int tid  = threadIdx.x;
    const int lane = tid & 31;
    const int wid  = tid >> 5;
    const int g    = wid >> 3;               // outer k-group (A buffer owner)
    const int wm   = (wid >> 1) & 3;         // m-tile (16 rows)
    const int wh   = wid & 1;                // inner s-split
    const int gtid = tid & 255;
    const int cta  = blockIdx.x;
    const int j0   = cta * JC;

    const __nv_bfloat16* wgh = Wh + (size_t)cta * NR * H_;
    const __nv_bfloat16* wgl = Wl + (size_t)cta * NR * H_;

    const int ar  = wm * 16 + (lane & 15);
    const int aca = lane >> 4;
    const int br_ = lane & 7;
    const int bca = (lane >> 3) & 1;

    // ---- load resident W (hi+lo, chunked 24x128B tiles) ----
#pragma unroll
    for (int i = 0; i < 6; i++) {
        int v = tid + i * 512;               // 0..3071
        int c = v / 192;
        int rem = v - c * 192;
        int r = rem >> 3, c8 = rem & 7;
        uint32_t so = rswz(r, c8);
        const size_t gsrc = (size_t)r * H_ + c * 64 + c8 * 8;
        cpasync16(sb + WH_OFF + c * 3072 + so, wgh + gsrc);
        cpasync16(sb + WL_OFF + c * 3072 + so, wgl + gsrc);
    }
    CP_COMMIT();

    if (tid < NR) bhhs[tid] = bhh[(tid >> 3) * H_ + j0 + (tid & 7)];
    {
        int b = tid >> 3, jj = tid & 7;
        float h0 = DEC ? dec_init[j0 + jj] : 0.f;
        h_s[tid] = h0;
        __nv_bfloat16 hh = __float2bfloat16(h0);
        __nv_bfloat16 hl = __float2bfloat16(h0 - __bfloat162float(hh));
        g_hb[0][0][b * H_ + j0 + jj] = hh;
        g_hb[0][1][b * H_ + j0 + jj] = hl;
    }
    // prefetch gx(0) + ctx
    if (tid < 384) {
        int b = tid / 6, rem = tid - b * 6, q = rem >> 1, sg = rem & 1;
        uint32_t doff = (uint32_t)(b * 24 + q * 8 + sg * 4) * 4;
        cpasync16(sb + SGX_OFF + doff, gx + (size_t)(b * T_) * G_ + q * H_ + j0 + sg * 4);
        if (DEC)
            cpasync16(sb + CTX_OFF + doff, ctxg + (size_t)b * G_ + q * H_ + j0 + sg * 4);
    }
    CP_COMMIT();
    CP_WAIT0();
    __syncthreads();
    if (tid == 0) {
        __threadfence();
        atomicAdd(&g_bar, 1);
        volatile int* vb = &g_bar;
        while (*vb < NCTA_R) __nanosleep(64);
        __threadfence();
    }
    __syncthreads();

    for (int t = 0; t < T_; t++) {
        const __nv_bfloat16 *pAh, *pAl;
        size_t astr;
        if (DEC) {
            if (t == 0) { pAh = g_hb[0][0]; pAl = g_hb[0][1]; astr = H_; }
            else {
                pAh = g_Ah + (size_t)(t - 1) * H_;
                pAl = g_Al + (size_t)(t - 1) * H_;
                astr = (size_t)T_ * H_;
            }
        } else {
            pAh = g_hb[t & 1][0]; pAl = g_hb[t & 1][1]; astr = H_;
        }

        auto rissue = [&](int buf, int chunk) {
            uint32_t s_ = sb + AB_OFF + (uint32_t)g * 32768u + (uint32_t)buf * 16384u;
            const __nv_bfloat16* ah = pAh + (size_t)chunk * RKC;
            const __nv_bfloat16* al = pAl + (size_t)chunk * RKC;
#pragma unroll
            for (int i_ = 0; i_ < 2; i_++) {
                int v_ = gtid + i_ * 256;
                int r_ = v_ >> 3, c8 = v_ & 7;
                uint32_t so_ = rswz(r_, c8);
                cpasync16(s_ + so_,         ah + (size_t)r_ * astr + c8 * 8);
                cpasync16(s_ + 8192u + so_, al + (size_t)r_ * astr + c8 * 8);
            }
        };

        float acc[3][4];
#pragma unroll
        for (int nt = 0; nt < 3; nt++)
#pragma unroll
            for (int q = 0; q < 4; q++) acc[nt][q] = 0.f;

        const int c0 = g * 8;
        rissue(0, c0);     CP_COMMIT();
        rissue(1, c0 + 1); CP_COMMIT();

#pragma unroll 1
        for (int kc = 0; kc < 8; kc++) {
            CP_WAIT1();
            GBAR(1 + g);
            const uint32_t abase = sb + AB_OFF + (uint32_t)g * 32768u + (uint32_t)(kc & 1) * 16384u;
            const uint32_t wch = (uint32_t)(c0 + kc) * 3072u;
#pragma unroll
            for (int ss = 0; ss < 2; ss++) {
                const int s = 2 * wh + ss;
                uint32_t aH[4], aL[4];
                uint32_t offA = (uint32_t)(ar * 128 + (((2 * s + aca) ^ (ar & 7)) << 4));
                ldsm4(aH, abase + offA);
                ldsm4(aL, abase + 8192u + offA);
#pragma unroll
                for (int nt = 0; nt < 3; nt++) {
                    int rb = nt * 8 + br_;
                    uint32_t offB = (uint32_t)(rb * 128 + (((2 * s + bca) ^ (rb & 7)) << 4));
                    uint32_t bH[2], bL[2];
                    ldsm2(bH, sb + WH_OFF + wch + offB);
                    ldsm2(bL, sb + WL_OFF + wch + offB);
                    mma_bf16(acc[nt], aH, bH);
                    mma_bf16(acc[nt], aH, bL);
                    mma_bf16(acc[nt], aL, bH);
                }
            }
            GBAR(1 + g);
            if (kc + 2 < 8) rissue(kc & 1, c0 + kc + 2);
            CP_COMMIT();
        }

        // prefetch gx(t+1)
        if (t + 1 < T_ && tid < 384) {
            int b = tid / 6, rem = tid - b * 6, q = rem >> 1, sg = rem & 1;
            uint32_t doff = (uint32_t)(((t + 1) & 1) * 1536 + b * 24 + q * 8 + sg * 4) * 4;
            cpasync16(sb + SGX_OFF + doff,
                      gx + (size_t)(b * T_ + t + 1) * G_ + q * H_ + j0 + sg * 4);
        }
        CP_COMMIT();

        // stage k-partial gh to smem: partition p = g*2+wh
        {
            float* sCp = sC + (g * 2 + wh) * 1792;
            int crow = wm * 16 + (lane >> 2);
            int ccol = (lane & 3) * 2;
#pragma unroll
            for (int nt = 0; nt < 3; nt++) {
                int cc = nt * 8 + ccol;
                *(float2*)&sCp[crow * 28 + cc]       = make_float2(acc[nt][0], acc[nt][1]);
                *(float2*)&sCp[(crow + 8) * 28 + cc] = make_float2(acc[nt][2], acc[nt][3]);
            }
        }
        __syncthreads();

        // gate: one item per thread
        const float* sgxt = sgx + (t & 1) * 1536;
        {
            int b = tid >> 3, jj = tid & 7;
            float ghr = bhhs[jj], ghz = bhhs[8 + jj], ghn = bhhs[16 + jj];
#pragma unroll
            for (int p = 0; p < 4; p++) {
                const float* sp = sC + p * 1792 + b * 28;
                ghr += sp[jj];
                ghz += sp[8 + jj];
                ghn += sp[16 + jj];
            }
            float xr = sgxt[b * 24 + jj];
            float xz = sgxt[b * 24 + 8 + jj];
            float xn = sgxt[b * 24 + 16 + jj];
            if (DEC) {
                xr += sctx[b * 24 + jj];
                xz += sctx[b * 24 + 8 + jj];
                xn += sctx[b * 24 + 16 + jj];
            }
            float r = 1.f / (1.f + expf(-(xr + ghr)));
            float z = 1.f / (1.f + expf(-(xz + ghz)));
            float n = tanhf(xn + r * ghn);
            float h2 = (1.f - z) * n + z * h_s[tid];
            h_s[tid] = h2;
            __nv_bfloat16 hh = __float2bfloat16(h2);
            __nv_bfloat16 hl = __float2bfloat16(h2 - __bfloat162float(hh));
            if (DEC) {
                size_t row = (size_t)(b * T_ + t) * H_ + j0 + jj;
                g_Ah[row] = hh;
                g_Al[row] = hl;
            } else {
                int gc = b * H_ + j0 + jj;
                g_hb[(t & 1) ^ 1][0][gc] = hh;
                g_hb[(t & 1) ^ 1][1][gc] = hl;
                if (t == T_ - 1) g_hfin[gc] = h2;
            }
        }
        __syncthreads();
        if (tid == 0) {
            __threadfence();
            atomicAdd(&g_bar, 1);
            int target = NCTA_R * (t + 2);
            volatile int* vb = &g_bar;
            while (*vb < target) __nanosleep(64);
            __threadfence();
        }
        __syncthreads();
    }
}

// ---------------- small fp32 NT GEMM for ctxg ----------------
__global__ __launch_bounds__(128) void gemm64_nt(
    const float* __restrict__ A, int lda,
    const float* __restrict__ Bm, int ldb,
    float* __restrict__ C, int ldc, int klen)
{
    __shared__ float As[16][64];
    __shared__ float Bs[16][32];

    const int tid = threadIdx.x;
    const int tx = tid & 7;
    const int ty = tid >> 3;
    const int n0 = blockIdx.x * 32;

    const int am0 = tid >> 2;
    const int am1 = am0 + 32;
    const int ak  = (tid & 3) * 4;

    const float* Ar0 = A + (size_t)am0 * lda;
    const float* Ar1 = A + (size_t)am1 * lda;
    const float* Br  = Bm + (size_t)(n0 + am0) * ldb;

    float acc[4][4];
#pragma unroll
    for (int i = 0; i < 4; i++)
#pragma unroll
        for (int j = 0; j < 4; j++) acc[i][j] = 0.f;

    for (int k0 = 0; k0 < klen; k0 += 16) {
        float4 a0 = *(const float4*)(Ar0 + k0 + ak);
        float4 a1 = *(const float4*)(Ar1 + k0 + ak);
        float4 b  = *(const float4*)(Br  + k0 + ak);

        __syncthreads();
        As[ak + 0][am0] = a0.x; As[ak + 1][am0] = a0.y; As[ak + 2][am0] = a0.z; As[ak + 3][am0] = a0.w;
        As[ak + 0][am1] = a1.x; As[ak + 1][am1] = a1.y; As[ak + 2][am1] = a1.z; As[ak + 3][am1] = a1.w;
        Bs[ak + 0][am0] = b.x;  Bs[ak + 1][am0] = b.y;  Bs[ak + 2][am0] = b.z;  Bs[ak + 3][am0] = b.w;
        __syncthreads();

#pragma unroll
        for (int kk = 0; kk < 16; kk++) {
            float4 av = *(const float4*)&As[kk][ty * 4];
            float4 bv = *(const float4*)&Bs[kk][tx * 4];
            float a[4] = {av.x, av.y, av.z, av.w};
            float b4[4] = {bv.x, bv.y, bv.z, bv.w};
#pragma unroll
            for (int i = 0; i < 4; i++)
#pragma unroll
                for (int j = 0; j < 4; j++) acc[i][j] += a[i] * b4[j];
        }
    }

#pragma unroll
    for (int i = 0; i < 4; i++) {
        int m = ty * 4 + i;
        float* crow = C + (size_t)m * ldc + n0 + tx * 4;
        *(float4*)crow = make_float4(acc[i][0], acc[i][1], acc[i][2], acc[i][3]);
    }
}

// ---------------- launch ----------------
extern "C" void kernel_launch(void* const* d_in, const int* in_sizes, int n_in,
                              void* d_out, int out_size)
{
    const int*   x        = (const int*)d_in[0];
    const int*   labels   = (const int*)d_in[1];
    const float* enc_emb  = (const float*)d_in[2];
    const float* enc_Wih  = (const float*)d_in[3];
    const float* enc_Whh  = (const float*)d_in[4];
    const float* enc_bih  = (const float*)d_in[5];
    const float* enc_bhh  = (const float*)d_in[6];
    const float* dec_emb  = (const float*)d_in[7];
    const float* dec_Wih  = (const float*)d_in[8];
    const float* dec_Whh  = (const float*)d_in[9];
    const float* dec_bih  = (const float*)d_in[10];
    const float* dec_bhh  = (const float*)d_in[11];
    const float* dec_init = (const float*)d_in[12];
    const float* lin_W    = (const float*)d_in[13];
    const float* lin_b    = (const float*)d_in[14];
    float* out = (float*)d_out;

    float *gx, *ctxg, *hfin;
    int *didx, *bar;
    __nv_bfloat16 *pAh, *pAl, *pBh, *pBl, *weH, *weL, *wdH, *wdL;
    cudaGetSymbolAddress((void**)&gx, g_gx);
    cudaGetSymbolAddress((void**)&ctxg, g_ctxg);
    cudaGetSymbolAddress((void**)&hfin, g_hfin);
    cudaGetSymbolAddress((void**)&didx, g_didx);
    cudaGetSymbolAddress((void**)&bar, g_bar);
    cudaGetSymbolAddress((void**)&pAh, g_Ah);
    cudaGetSymbolAddress((void**)&pAl, g_Al);
    cudaGetSymbolAddress((void**)&pBh, g_Bh);
    cudaGetSymbolAddress((void**)&pBl, g_Bl);
    cudaGetSymbolAddress((void**)&weH, g_WencH);
    cudaGetSymbolAddress((void**)&weL, g_WencL);
    cudaGetSymbolAddress((void**)&wdH, g_WdecH);
    cudaGetSymbolAddress((void**)&wdL, g_WdecL);

    const int hmma_smem = 2 * STAGE_B;
    cudaFuncSetAttribute(hmma_nt<512>,  cudaFuncAttributeMaxDynamicSharedMemorySize, hmma_smem);
    cudaFuncSetAttribute(hmma_nt<1024>, cudaFuncAttributeMaxDynamicSharedMemorySize, hmma_smem);
    cudaFuncSetAttribute(recur<false>, cudaFuncAttributeMaxDynamicSharedMemorySize, SMEM_REC);
    cudaFuncSetAttribute(recur<true>,  cudaFuncAttributeMaxDynamicSharedMemorySize, SMEM_REC);

    // one-time weight conversions
    whh_split<<<dim3(NCTA_R, NR), 256>>>(enc_Whh, weH, weL);
    whh_split<<<dim3(NCTA_R, NR), 256>>>(dec_Whh, wdH, wdL);

    // encoder input gates
    split_stride<<<G_, 128>>>(enc_Wih, E_, pBh, pBl, E_);
    gather_split<<<MT_, 128>>>(enc_emb, x, pAh, pAl);
    hmma_nt<512><<<dim3(MT_ / 128, G_ / 128), 256, hmma_smem>>>(
        pAh, pAl, pBh, pBl, enc_bih, gx, G_);

    // encoder recurrence
    cudaMemsetAsync(bar, 0, sizeof(int));
    recur<false><<<NCTA_R, 512, SMEM_REC>>>(weH, weL, gx, enc_bhh, nullptr, nullptr);

    // ctx gate contribution
    gemm64_nt<<<G_ / 32, 128>>>(hfin, H_, dec_Wih + E_, DI_, ctxg, G_, H_);

    // decoder input gates
    build_didx<<<MT_ / 256, 256>>>(labels);
    gather_split<<<MT_, 128>>>(dec_emb, didx, pAh, pAl);
    split_stride<<<G_, 128>>>(dec_Wih, DI_, pBh, pBl, E_);
    hmma_nt<512><<<dim3(MT_ / 128, G_ / 128), 256, hmma_smem>>>(
        pAh, pAl, pBh, pBl, dec_bih, gx, G_);

    // decoder recurrence (writes bf16 hi/lo states directly into g_Ah/g_Al)
    cudaMemsetAsync(bar, 0, sizeof(int));
    recur<true><<<NCTA_R, 512, SMEM_REC>>>(wdH, wdL, gx, dec_bhh, ctxg, dec_init);

    // logits
    split_bf16<<<((int)((size_t)V_ * H_ / 4) + 255) / 256, 256>>>(
        lin_W, pBh, pBl, (int)((size_t)V_ * H_ / 4));
    hmma_nt<1024><<<dim3(MT_ / 128, V_ / 128), 256, hmma_smem>>>(
        pAh, pAl, pBh, pBl, lin_b, out, V_);
}